// round 11
// baseline (speedup 1.0000x reference)
#include <cuda_runtime.h>
#include <cuda_bf16.h>
#include <cstdint>
#include <math.h>

#define BATCH 8
#define CIN   256
#define MCH   256
#define OCH   256
#define HH    128
#define WW    128
#define HWPX  16384
#define KSEL  128

// ---------------- device scratch ----------------
__device__ __align__(128) __nv_bfloat16 gXb[(size_t)BATCH * CIN * HWPX];           // x bf16
__device__ __align__(128) __nv_bfloat16 g_selb[(size_t)BATCH * KSEL * HWPX];       // relu(h)[:,:128] bf16
__device__ __align__(128) __nv_bfloat16 g_fusedb[(size_t)BATCH * 3 * KSEL * HWPX]; // dwconv out bf16
__device__ __align__(128) __nv_bfloat16 gA1[256 * 256];                            // pw1_w bf16 linear
__device__ __align__(128) __nv_bfloat16 gA2[256 * 384];                            // pw_w[:, :384] bf16 linear
__device__ float gXmean[BATCH * CIN];
__device__ float g_gap2_part[BATCH * MCH * 128];
__device__ float g_gapv[BATCH * MCH];
__device__ float g_gap2v[BATCH * MCH];
__device__ float g_hidv[BATCH * 512];
__device__ float g_scorev[BATCH * MCH];
__device__ float g_w3[BATCH * KSEL * 9];
__device__ float g_w5[BATCH * KSEL * 25];
__device__ float g_w7[BATCH * KSEL * 49];

// ---------------- PTX helpers (baseline compute_103 features only) ----------------
__device__ __forceinline__ uint32_t smem_u32(const void* p) {
    uint32_t a;
    asm("{ .reg .u64 t; cvta.to.shared.u64 t, %1; cvt.u32.u64 %0, t; }" : "=r"(a) : "l"(p));
    return a;
}
__device__ __forceinline__ void cp16(uint32_t dst, const void* src) {
    asm volatile("cp.async.cg.shared.global [%0], [%1], 16;" :: "r"(dst), "l"(src) : "memory");
}
__device__ __forceinline__ void cp_commit() { asm volatile("cp.async.commit_group;" ::: "memory"); }
template<int N> __device__ __forceinline__ void cp_wait() { asm volatile("cp.async.wait_group %0;" :: "n"(N) : "memory"); }

__device__ __forceinline__ void ldsm_x4(uint32_t* r, uint32_t addr) {
    asm volatile("ldmatrix.sync.aligned.m8n8.x4.shared.b16 {%0,%1,%2,%3}, [%4];"
                 : "=r"(r[0]), "=r"(r[1]), "=r"(r[2]), "=r"(r[3]) : "r"(addr));
}
__device__ __forceinline__ void ldsm_x4_t(uint32_t* r, uint32_t addr) {
    asm volatile("ldmatrix.sync.aligned.m8n8.x4.trans.shared.b16 {%0,%1,%2,%3}, [%4];"
                 : "=r"(r[0]), "=r"(r[1]), "=r"(r[2]), "=r"(r[3]) : "r"(addr));
}
__device__ __forceinline__ void mma16816(float* d, const uint32_t* a, const uint32_t* b) {
    asm volatile("mma.sync.aligned.m16n8k16.row.col.f32.bf16.bf16.f32 "
                 "{%0,%1,%2,%3}, {%4,%5,%6,%7}, {%8,%9}, {%0,%1,%2,%3};"
                 : "+f"(d[0]), "+f"(d[1]), "+f"(d[2]), "+f"(d[3])
                 : "r"(a[0]), "r"(a[1]), "r"(a[2]), "r"(a[3]), "r"(b[0]), "r"(b[1]));
}
__device__ __forceinline__ float wred(float v) {
    v += __shfl_xor_sync(0xffffffffu, v, 16);
    v += __shfl_xor_sync(0xffffffffu, v, 8);
    v += __shfl_xor_sync(0xffffffffu, v, 4);
    v += __shfl_xor_sync(0xffffffffu, v, 2);
    v += __shfl_xor_sync(0xffffffffu, v, 1);
    return v;
}
// packed fp32x2 helpers (sm_100+ PTX, full fp32 per lane)
__device__ __forceinline__ uint64_t pk2(float lo, float hi) {
    uint64_t r;
    asm("mov.b64 %0, {%1, %2};" : "=l"(r) : "f"(lo), "f"(hi));
    return r;
}
__device__ __forceinline__ void upk2(uint64_t v, float& lo, float& hi) {
    asm("mov.b64 {%0, %1}, %2;" : "=f"(lo), "=f"(hi) : "l"(v));
}
__device__ __forceinline__ void ffma2(uint64_t& d, uint64_t a, uint64_t b) {
    asm("fma.rn.f32x2 %0, %1, %2, %0;" : "+l"(d) : "l"(a), "l"(b));
}

// =====================================================================
// kxc: x fp32 -> bf16 + exact fp32 row means (score path stays exact)
// =====================================================================
__global__ __launch_bounds__(256) void kxc(const float* __restrict__ x)
{
    __shared__ float red[256];
    const int row = blockIdx.x;
    const int t = threadIdx.x;
    const float4* in4 = (const float4*)(x + (size_t)row * HWPX);
    __nv_bfloat162* ob = (__nv_bfloat162*)(gXb + (size_t)row * HWPX);
    float s = 0.f;
#pragma unroll
    for (int it = 0; it < 16; it++) {
        int j = t + it * 256;
        float4 v = in4[j];
        s += v.x + v.y + v.z + v.w;
        ob[j * 2 + 0] = __floats2bfloat162_rn(v.x, v.y);
        ob[j * 2 + 1] = __floats2bfloat162_rn(v.z, v.w);
    }
    red[t] = s;
    __syncthreads();
    for (int o = 128; o > 0; o >>= 1) {
        if (t < o) red[t] += red[t + o];
        __syncthreads();
    }
    if (t == 0) gXmean[row] = red[0] * (1.f / (float)HWPX);
}

// =====================================================================
// kprep: weights -> bf16 linear row-major images
// =====================================================================
__global__ __launch_bounds__(256) void kprep(const float* __restrict__ pw1_w,
                                             const float* __restrict__ pw_w)
{
    int i = blockIdx.x * 256 + threadIdx.x;
    if (i < 65536) {
        gA1[i] = __float2bfloat16(pw1_w[i]);
    } else {
        int j = i - 65536;            // 256 rows x 384 cols
        int m = j / 384, k = j % 384;
        gA2[j] = __float2bfloat16(pw_w[m * 768 + k]);
    }
}

// =====================================================================
// kgemm<KDIM, EP> (persistent CTAs, R10): mma.sync bf16 GEMM at the
// HMMA issue ceiling — do not touch.
// grid (16, 1, BATCH), 256 threads.
// =====================================================================
template<int KDIM, int EP>
__global__ __launch_bounds__(256, 1)
void kgemm(const __nv_bfloat16* __restrict__ Aimg,
           const __nv_bfloat16* __restrict__ Bsrc,
           const float* __restrict__ bias,
           const float* __restrict__ xres,
           float* __restrict__ out)
{
    constexpr int KC = 64;
    constexpr int NCHUNK = KDIM / KC;
    constexpr int NBLK = 8;                  // p-blocks per CTA
    constexpr int TOTCH = NBLK * NCHUNK;     // flat chunk count
    constexpr int ASZ = 256 * KDIM * 2;      // bytes (256 m-rows)
    constexpr int BROW = 256;                // bytes per B k-row (128 bf16)
    constexpr int BSZ = KC * BROW;           // 16KB per buffer

    extern __shared__ char sraw[];
    const uint32_t rawu = smem_u32(sraw);
    const uint32_t sbase = (rawu + 127u) & ~127u;
    const uint32_t uA = sbase;
    const uint32_t uB = sbase + ASZ;
    float* sg = (float*)(sraw + (sbase - rawu) + ASZ + 2 * BSZ);   // [4][256] (EP1)

    const int t = threadIdx.x, wid = t >> 5, lane = t & 31;
    const int b = blockIdx.z;
    const int pcBase = blockIdx.x * NBLK;
    const int wm = (wid >> 2) * 128;         // warp m offset (0 or 128)
    const int wp = (wid & 3) * 32;           // warp p offset

    const char* Bb = (const char*)(Bsrc + (size_t)b * KDIM * HWPX);
    const char* Ab = (const char*)Aimg;

    auto loadB = [&](int buf, int chunk) {
        const int blk2 = chunk / NCHUNK;
        const int kc0 = (chunk % NCHUNK) * KC;
        const int p0n = (pcBase + blk2) * 128;
        uint32_t dst = uB + buf * BSZ;
#pragma unroll
        for (int i = t; i < KC * 16; i += 256) {
            int k = i >> 4, j = i & 15;
            cp16(dst + k * BROW + ((j * 16) ^ ((k & 7) << 4)),
                 Bb + ((size_t)(kc0 + k) * HWPX + p0n) * 2 + j * 16);
        }
    };

    {
        constexpr int CPR = KDIM / 8;        // 16B chunks per row
        for (int i = t; i < 256 * CPR; i += 256) {
            int m = i / CPR, j = i % CPR;
            cp16(uA + m * (KDIM * 2) + ((j * 16) ^ ((m & 7) << 4)),
                 Ab + (size_t)m * (KDIM * 2) + j * 16);
        }
    }
    loadB(0, 0);
    cp_commit();
    loadB(1, 1);
    cp_commit();

    float acc[8][4][4];
#pragma unroll
    for (int mi = 0; mi < 8; mi++)
#pragma unroll
        for (int ni = 0; ni < 4; ni++)
#pragma unroll
            for (int r = 0; r < 4; r++) acc[mi][ni][r] = 0.f;

    const int a_m  = wm + (lane & 15);
    const int a_kb = (lane >> 4) * 16;
    const uint32_t aBase = uA + a_m * (KDIM * 2);
    const uint32_t aSwz  = (a_m & 7) << 4;
    const int b_k  = lane & 15;
    const int b_nb = wp * 2 + (lane >> 4) * 16;
    const uint32_t bSwzK = (b_k & 7) << 4;

    const int erow = lane >> 2;
    const int ecol = (lane & 3) * 2;

    for (int jj = 0; jj < TOTCH; jj++) {
        const int blk = jj / NCHUNK;
        const int c = jj % NCHUNK;
        const int p0 = (pcBase + blk) * 128;

        if (jj == TOTCH - 1) cp_wait<0>(); else cp_wait<1>();
        __syncthreads();

        const uint32_t bb = uB + (jj & 1) * BSZ + b_k * BROW;
#pragma unroll
        for (int ks = 0; ks < KC / 16; ks++) {
            const int kB = ks * 32;
            uint32_t bf[2][4];
#pragma unroll
            for (int h = 0; h < 2; h++)
                ldsm_x4_t(bf[h], bb + ks * 16 * BROW + ((b_nb + h * 32) ^ bSwzK));
#pragma unroll
            for (int mi = 0; mi < 8; mi++) {
                uint32_t a[4];
                ldsm_x4(a, aBase + mi * 16 * (KDIM * 2) +
                           (((c * KC * 2) + kB + a_kb) ^ aSwz));
#pragma unroll
                for (int ni = 0; ni < 4; ni++)
                    mma16816(acc[mi][ni], a, &bf[ni >> 1][(ni & 1) * 2]);
            }
        }
        __syncthreads();
        if (jj + 2 < TOTCH) { loadB(jj & 1, jj + 2); cp_commit(); }

        if (c == NCHUNK - 1) {
            const int pc = pcBase + blk;
            if (EP == 2) {
#pragma unroll
                for (int mi = 0; mi < 8; mi++) {
#pragma unroll
                    for (int h = 0; h < 2; h++) {
                        const int m = wm + mi * 16 + h * 8 + erow;
                        const float bv = bias[m];
                        const size_t rb = ((size_t)(b * OCH + m)) * HWPX + p0;
#pragma unroll
                        for (int ni = 0; ni < 4; ni++) {
                            const size_t o = rb + wp + ni * 8 + ecol;
                            float2 xr = *(const float2*)&xres[o];
                            float2 v;
                            v.x = acc[mi][ni][2 * h]     + bv + xr.x;
                            v.y = acc[mi][ni][2 * h + 1] + bv + xr.y;
                            *(float2*)&out[o] = v;
                        }
                    }
                }
            } else {
                float rs[8][2];
#pragma unroll
                for (int mi = 0; mi < 8; mi++) {
#pragma unroll
                    for (int h = 0; h < 2; h++) {
                        const int m = wm + mi * 16 + h * 8 + erow;
                        const float bv = bias[m];
                        float s2 = 0.f;
#pragma unroll
                        for (int ni = 0; ni < 4; ni++) {
                            float v0 = fmaxf(acc[mi][ni][2 * h]     + bv, 0.f);
                            float v1 = fmaxf(acc[mi][ni][2 * h + 1] + bv, 0.f);
                            s2 += v0 + v1;
                            if (m < KSEL) {
                                size_t o = ((size_t)(b * KSEL + m)) * HWPX + p0 + wp + ni * 8 + ecol;
                                *(__nv_bfloat162*)&g_selb[o] = __floats2bfloat162_rn(v0, v1);
                            }
                        }
                        rs[mi][h] = s2;
                    }
                }
#pragma unroll
                for (int mi = 0; mi < 8; mi++)
#pragma unroll
                    for (int h = 0; h < 2; h++) {
                        rs[mi][h] += __shfl_xor_sync(0xffffffffu, rs[mi][h], 1);
                        rs[mi][h] += __shfl_xor_sync(0xffffffffu, rs[mi][h], 2);
                    }
                if ((lane & 3) == 0) {
#pragma unroll
                    for (int mi = 0; mi < 8; mi++)
#pragma unroll
                        for (int h = 0; h < 2; h++)
                            sg[(wid & 3) * 256 + wm + mi * 16 + h * 8 + erow] = rs[mi][h];
                }
                __syncthreads();
                g_gap2_part[(b * MCH + t) * 128 + pc] =
                    sg[t] + sg[256 + t] + sg[512 + t] + sg[768 + t];
            }
#pragma unroll
            for (int mi = 0; mi < 8; mi++)
#pragma unroll
                for (int ni = 0; ni < 4; ni++)
#pragma unroll
                    for (int r = 0; r < 4; r++) acc[mi][ni][r] = 0.f;
        }
    }
}

// =====================================================================
// k2a: gap (exact, from xmean) + gap2 partial reduce. grid 288.
// =====================================================================
__global__ __launch_bounds__(256) void k2a(const float* __restrict__ pw1_w,
                                           const float* __restrict__ pw1_b)
{
    const int t = threadIdx.x, wid = t >> 5, lane = t & 31;
    if (blockIdx.x < 32) {
        __shared__ float sxm[2048];
        for (int i = t; i < 2048; i += 256) sxm[i] = gXmean[i];
        __syncthreads();
        const int m = blockIdx.x * 8 + wid;
        const float* wr = pw1_w + m * CIN;
        float acc[8] = {0.f, 0.f, 0.f, 0.f, 0.f, 0.f, 0.f, 0.f};
        for (int c = lane; c < CIN; c += 32) {
            float w = wr[c];
#pragma unroll
            for (int bb = 0; bb < 8; bb++) acc[bb] = fmaf(sxm[bb * 256 + c], w, acc[bb]);
        }
#pragma unroll
        for (int bb = 0; bb < 8; bb++) acc[bb] = wred(acc[bb]);
        if (lane == 0) {
            float bv = pw1_b[m];
#pragma unroll
            for (int bb = 0; bb < 8; bb++) g_gapv[bb * 256 + m] = acc[bb] + bv;
        }
    } else {
        const int rr = (blockIdx.x - 32) * 8 + wid;
        const float4* p4 = (const float4*)(g_gap2_part + (size_t)rr * 128);
        float4 v = p4[lane];
        float a = wred(v.x + v.y + v.z + v.w);
        if (lane == 0) g_gap2v[rr] = a * (1.f / (float)HWPX);
    }
}

// =====================================================================
// k2b: fc1 (512 outputs x 8 batches). grid 64, warp per j.
// =====================================================================
__global__ __launch_bounds__(256) void k2b(const float* __restrict__ fc1_w,
                                           const float* __restrict__ fc1_b)
{
    __shared__ float sgap[2048];
    const int t = threadIdx.x, wid = t >> 5, lane = t & 31;
    for (int i = t; i < 2048; i += 256) sgap[i] = g_gapv[i];
    __syncthreads();
    const int j = blockIdx.x * 8 + wid;
    const float* wr = fc1_w + j * MCH;
    float acc[8] = {0.f, 0.f, 0.f, 0.f, 0.f, 0.f, 0.f, 0.f};
    for (int c = lane; c < MCH; c += 32) {
        float w = wr[c];
#pragma unroll
        for (int bb = 0; bb < 8; bb++) acc[bb] = fmaf(sgap[bb * 256 + c], w, acc[bb]);
    }
#pragma unroll
    for (int bb = 0; bb < 8; bb++) acc[bb] = wred(acc[bb]);
    if (lane == 0) {
        float bv = fc1_b[j];
#pragma unroll
        for (int bb = 0; bb < 8; bb++) g_hidv[bb * 512 + j] = fmaxf(acc[bb] + bv, 0.f);
    }
}

// =====================================================================
// k2c: fc2 + sigmoid (256 outputs x 8 batches). grid 32, warp per j.
// =====================================================================
__global__ __launch_bounds__(256) void k2c(const float* __restrict__ fc2_w,
                                           const float* __restrict__ fc2_b)
{
    __shared__ float shid[4096];
    const int t = threadIdx.x, wid = t >> 5, lane = t & 31;
    for (int i = t; i < 4096; i += 256) shid[i] = g_hidv[i];
    __syncthreads();
    const int j = blockIdx.x * 8 + wid;
    const float* wr = fc2_w + j * 512;
    float acc[8] = {0.f, 0.f, 0.f, 0.f, 0.f, 0.f, 0.f, 0.f};
    for (int c = lane; c < 512; c += 32) {
        float w = wr[c];
#pragma unroll
        for (int bb = 0; bb < 8; bb++) acc[bb] = fmaf(shid[bb * 512 + c], w, acc[bb]);
    }
#pragma unroll
    for (int bb = 0; bb < 8; bb++) acc[bb] = wred(acc[bb]);
    if (lane == 0) {
        float bv = fc2_b[j];
#pragma unroll
        for (int bb = 0; bb < 8; bb++)
            g_scorev[bb * 256 + j] = 1.f / (1.f + expf(-(acc[bb] + bv)));
    }
}

// =====================================================================
// k2d: top-k mask + offsets + effective depthwise weights. grid 64.
// =====================================================================
__global__ __launch_bounds__(256) void k2d(const float* __restrict__ off_w,
                                           const float* __restrict__ off_b,
                                           const float* __restrict__ dw3,
                                           const float* __restrict__ dw5,
                                           const float* __restrict__ dw7)
{
    __shared__ float ssc[256], sg2[256], smask[128], sscl[3], ssht[3];
    const int t = threadIdx.x, wid = t >> 5, lane = t & 31;
    const int bb = blockIdx.x >> 3, slice = blockIdx.x & 7;

    ssc[t] = g_scorev[bb * 256 + t];
    sg2[t] = g_gap2v[bb * 256 + t];
    __syncthreads();

    if (wid < 6) {
        const int r = wid;
        const float* wr = off_w + r * MCH;
        float a = 0.f;
        for (int c = lane; c < MCH; c += 32) a = fmaf(sg2[c], wr[c], a);
        a = wred(a);
        if (lane == 0) {
            float o = tanhf(a + off_b[r]);
            if ((r & 1) == 0) sscl[r >> 1] = 1.f / (1.f + expf(-o));
            else              ssht[r >> 1] = tanhf(o);
        }
    }
    if (t < KSEL) {
        float sc = ssc[t];
        int cnt = 0;
        for (int j = 0; j < MCH; j++) {
            float sj = ssc[j];
            cnt += (sj > sc) || (sj == sc && j < t);
        }
        smask[t] = (cnt < KSEL) ? 1.f : 0.f;
    }
    __syncthreads();

    for (int i = slice * 256 + t; i < 1152; i += 2048) {
        int c = i / 9;
        g_w3[bb * 1152 + i] = fmaf(dw3[i], 1.f + sscl[0], ssht[0]) * smask[c];
    }
    for (int i = slice * 256 + t; i < 3200; i += 2048) {
        int c = i / 25;
        g_w5[bb * 3200 + i] = fmaf(dw5[i], 1.f + sscl[1], ssht[1]) * smask[c];
    }
    for (int i = slice * 256 + t; i < 6272; i += 2048) {
        int c = i / 49;
        g_w7[bb * 6272 + i] = fmaf(dw7[i], 1.f + sscl[2], ssht[2]) * smask[c];
    }
}

// =====================================================================
// k3 (R11): fused depthwise 3x3+5x5+7x7, TWO BATCHES packed per lane
// via fma.rn.f32x2 (FFMA2). smem holds float2{b0,b1} per pixel; weights
// pre-packed per batch-pair. Per-output fp32 op order identical to R8
// -> bit-identical results. grid (16, 128, 4), 256 threads.
// =====================================================================
__global__ __launch_bounds__(256) void k3_dwconv()
{
    __shared__ float2 s2[38][40];
    __shared__ uint64_t sw2[84];

    const int bz = blockIdx.z;
    const int b0 = bz * 2, b1 = bz * 2 + 1;
    const int c = blockIdx.y;
    const int tile = blockIdx.x;
    const int ty0 = (tile >> 2) * 32;
    const int tx0 = (tile & 3) * 32;
    const int t = threadIdx.x;

    const __nv_bfloat16* in0 = g_selb + ((size_t)(b0 * KSEL + c)) * HWPX;
    const __nv_bfloat16* in1 = g_selb + ((size_t)(b1 * KSEL + c)) * HWPX;

    for (int i = t; i < 38 * 38; i += 256) {
        int r = i / 38, cc = i % 38;
        int gy = ty0 + r - 3, gx = tx0 + cc - 3;
        bool ok = (gy >= 0 && gy < HH && gx >= 0 && gx < WW);
        float v0 = ok ? __bfloat162float(in0[gy * WW + gx]) : 0.f;
        float v1 = ok ? __bfloat162float(in1[gy * WW + gx]) : 0.f;
        s2[r][cc] = make_float2(v0, v1);
    }
    if (t < 9) {
        sw2[t] = pk2(g_w3[(b0 * KSEL + c) * 9 + t], g_w3[(b1 * KSEL + c) * 9 + t]);
    } else if (t < 34) {
        int j = t - 9;
        sw2[t] = pk2(g_w5[(b0 * KSEL + c) * 25 + j], g_w5[(b1 * KSEL + c) * 25 + j]);
    } else if (t < 83) {
        int j = t - 34;
        sw2[t] = pk2(g_w7[(b0 * KSEL + c) * 49 + j], g_w7[(b1 * KSEL + c) * 49 + j]);
    }
    __syncthreads();

    const int py  = t >> 3;          // 0..31
    const int px0 = (t & 7) * 4;     // 0,4,...,28

    uint64_t A3[4] = {0ull, 0ull, 0ull, 0ull};
    uint64_t A5[4] = {0ull, 0ull, 0ull, 0ull};
    uint64_t A7[4] = {0ull, 0ull, 0ull, 0ull};

#pragma unroll
    for (int dy = 0; dy < 7; dy++) {
        const ulonglong2* rowq = (const ulonglong2*)&s2[py + dy][px0];
        uint64_t w2[12];
#pragma unroll
        for (int q = 0; q < 6; q++) {
            ulonglong2 v = rowq[q];
            w2[2 * q] = v.x;
            w2[2 * q + 1] = v.y;
        }
#pragma unroll
        for (int dx = 0; dx < 7; dx++) {
            uint64_t wt = sw2[34 + dy * 7 + dx];
#pragma unroll
            for (int j = 0; j < 4; j++) ffma2(A7[j], w2[j + dx], wt);
        }
        if (dy >= 1 && dy <= 5) {
#pragma unroll
            for (int dx = 0; dx < 5; dx++) {
                uint64_t wt = sw2[9 + (dy - 1) * 5 + dx];
#pragma unroll
                for (int j = 0; j < 4; j++) ffma2(A5[j], w2[j + 1 + dx], wt);
            }
        }
        if (dy >= 2 && dy <= 4) {
#pragma unroll
            for (int dx = 0; dx < 3; dx++) {
                uint64_t wt = sw2[(dy - 2) * 3 + dx];
#pragma unroll
                for (int j = 0; j < 4; j++) ffma2(A3[j], w2[j + 2 + dx], wt);
            }
        }
    }

    const size_t base = (size_t)(ty0 + py) * WW + tx0 + px0;
    const size_t ob0 = ((size_t)(b0 * (3 * KSEL) + c)) * HWPX + base;
    const size_t ob1 = ((size_t)(b1 * (3 * KSEL) + c)) * HWPX + base;

#pragma unroll
    for (int ks = 0; ks < 3; ks++) {
        const uint64_t* A = (ks == 0) ? A3 : (ks == 1) ? A5 : A7;
        float l0, h0, l1, h1, l2, h2, l3, h3;
        upk2(A[0], l0, h0); upk2(A[1], l1, h1);
        upk2(A[2], l2, h2); upk2(A[3], l3, h3);
        const size_t off = (size_t)ks * KSEL * HWPX;
        __nv_bfloat162 p0 = __floats2bfloat162_rn(l0, l1);
        __nv_bfloat162 p1 = __floats2bfloat162_rn(l2, l3);
        *(uint2*)&g_fusedb[ob0 + off] = make_uint2(*(uint32_t*)&p0, *(uint32_t*)&p1);
        p0 = __floats2bfloat162_rn(h0, h1);
        p1 = __floats2bfloat162_rn(h2, h3);
        *(uint2*)&g_fusedb[ob1 + off] = make_uint2(*(uint32_t*)&p0, *(uint32_t*)&p1);
    }
}

// =====================================================================
extern "C" void kernel_launch(void* const* d_in, const int* in_sizes, int n_in,
                              void* d_out, int out_size)
{
    const float* x     = (const float*)d_in[0];
    const float* pw1_w = (const float*)d_in[1];
    const float* pw1_b = (const float*)d_in[2];
    const float* fc1_w = (const float*)d_in[3];
    const float* fc1_b = (const float*)d_in[4];
    const float* fc2_w = (const float*)d_in[5];
    const float* fc2_b = (const float*)d_in[6];
    const float* off_w = (const float*)d_in[7];
    const float* off_b = (const float*)d_in[8];
    const float* dw3   = (const float*)d_in[9];
    const float* dw5   = (const float*)d_in[10];
    const float* dw7   = (const float*)d_in[11];
    const float* pw_w  = (const float*)d_in[12];
    const float* pw_b  = (const float*)d_in[13];
    float* out = (float*)d_out;

    const int smem1 = 256 * 256 * 2 + 2 * 16384 + 4 * 256 * 4 + 256;   // 168192
    const int smem2 = 256 * 384 * 2 + 2 * 16384 + 256;                  // 229632
    cudaFuncSetAttribute((const void*)kgemm<256, 1>, cudaFuncAttributeMaxDynamicSharedMemorySize, smem1);
    cudaFuncSetAttribute((const void*)kgemm<384, 2>, cudaFuncAttributeMaxDynamicSharedMemorySize, smem2);

    __nv_bfloat16 *gA1p, *gA2p, *gXbp, *gFbp;
    cudaGetSymbolAddress((void**)&gA1p, gA1);
    cudaGetSymbolAddress((void**)&gA2p, gA2);
    cudaGetSymbolAddress((void**)&gXbp, gXb);
    cudaGetSymbolAddress((void**)&gFbp, g_fusedb);

    kxc<<<BATCH * CIN, 256>>>(x);
    kprep<<<640, 256>>>(pw1_w, pw_w);
    kgemm<256, 1><<<dim3(16, 1, BATCH), 256, smem1>>>(gA1p, gXbp, pw1_b, nullptr, nullptr);
    k2a<<<288, 256>>>(pw1_w, pw1_b);
    k2b<<<64, 256>>>(fc1_w, fc1_b);
    k2c<<<32, 256>>>(fc2_w, fc2_b);
    k2d<<<64, 256>>>(off_w, off_b, dw3, dw5, dw7);
    k3_dwconv<<<dim3(16, KSEL, BATCH / 2), 256>>>();
    kgemm<384, 2><<<dim3(16, 1, BATCH), 256, smem2>>>(gA2p, gFbp, pw_b, x, out);
}

// round 12
// speedup vs baseline: 1.6515x; 1.6515x over previous
#include <cuda_runtime.h>
#include <cuda_bf16.h>
#include <cstdint>
#include <math.h>

#define BATCH 8
#define CIN   256
#define MCH   256
#define OCH   256
#define HH    128
#define WW    128
#define HWPX  16384
#define KSEL  128

// ---------------- device scratch ----------------
__device__ __align__(128) __nv_bfloat16 gXb[(size_t)BATCH * CIN * HWPX];           // x bf16
__device__ __align__(128) __nv_bfloat16 g_selb[(size_t)BATCH * KSEL * HWPX];       // relu(h)[:,:128] bf16
__device__ __align__(128) __nv_bfloat16 g_fusedb[(size_t)BATCH * 3 * KSEL * HWPX]; // dwconv out bf16
__device__ __align__(128) __nv_bfloat16 gA1[256 * 256];                            // pw1_w bf16 linear
__device__ __align__(128) __nv_bfloat16 gA2[256 * 384];                            // pw_w[:, :384] bf16 linear
__device__ float gXmean[BATCH * CIN];
__device__ float g_gap2_part[BATCH * MCH * 128];
__device__ float g_gapv[BATCH * MCH];
__device__ float g_gap2v[BATCH * MCH];
__device__ float g_hidv[BATCH * 512];
__device__ float g_scorev[BATCH * MCH];
__device__ float g_maskv[BATCH * KSEL];
__device__ float g_w3[BATCH * KSEL * 9];
__device__ float g_w5[BATCH * KSEL * 25];
__device__ float g_w7[BATCH * KSEL * 49];

// ---------------- PTX helpers (baseline compute_103 features only) ----------------
__device__ __forceinline__ uint32_t smem_u32(const void* p) {
    uint32_t a;
    asm("{ .reg .u64 t; cvta.to.shared.u64 t, %1; cvt.u32.u64 %0, t; }" : "=r"(a) : "l"(p));
    return a;
}
__device__ __forceinline__ void cp16(uint32_t dst, const void* src) {
    asm volatile("cp.async.cg.shared.global [%0], [%1], 16;" :: "r"(dst), "l"(src) : "memory");
}
__device__ __forceinline__ void cp_commit() { asm volatile("cp.async.commit_group;" ::: "memory"); }
template<int N> __device__ __forceinline__ void cp_wait() { asm volatile("cp.async.wait_group %0;" :: "n"(N) : "memory"); }

__device__ __forceinline__ void ldsm_x4(uint32_t* r, uint32_t addr) {
    asm volatile("ldmatrix.sync.aligned.m8n8.x4.shared.b16 {%0,%1,%2,%3}, [%4];"
                 : "=r"(r[0]), "=r"(r[1]), "=r"(r[2]), "=r"(r[3]) : "r"(addr));
}
__device__ __forceinline__ void ldsm_x4_t(uint32_t* r, uint32_t addr) {
    asm volatile("ldmatrix.sync.aligned.m8n8.x4.trans.shared.b16 {%0,%1,%2,%3}, [%4];"
                 : "=r"(r[0]), "=r"(r[1]), "=r"(r[2]), "=r"(r[3]) : "r"(addr));
}
__device__ __forceinline__ void mma16816(float* d, const uint32_t* a, const uint32_t* b) {
    asm volatile("mma.sync.aligned.m16n8k16.row.col.f32.bf16.bf16.f32 "
                 "{%0,%1,%2,%3}, {%4,%5,%6,%7}, {%8,%9}, {%0,%1,%2,%3};"
                 : "+f"(d[0]), "+f"(d[1]), "+f"(d[2]), "+f"(d[3])
                 : "r"(a[0]), "r"(a[1]), "r"(a[2]), "r"(a[3]), "r"(b[0]), "r"(b[1]));
}
__device__ __forceinline__ float wred(float v) {
    v += __shfl_xor_sync(0xffffffffu, v, 16);
    v += __shfl_xor_sync(0xffffffffu, v, 8);
    v += __shfl_xor_sync(0xffffffffu, v, 4);
    v += __shfl_xor_sync(0xffffffffu, v, 2);
    v += __shfl_xor_sync(0xffffffffu, v, 1);
    return v;
}

// =====================================================================
// kxc: x fp32 -> bf16 + exact fp32 row means (score path stays exact)
// =====================================================================
__global__ __launch_bounds__(256) void kxc(const float* __restrict__ x)
{
    __shared__ float red[256];
    const int row = blockIdx.x;
    const int t = threadIdx.x;
    const float4* in4 = (const float4*)(x + (size_t)row * HWPX);
    __nv_bfloat162* ob = (__nv_bfloat162*)(gXb + (size_t)row * HWPX);
    float s = 0.f;
#pragma unroll
    for (int it = 0; it < 16; it++) {
        int j = t + it * 256;
        float4 v = in4[j];
        s += v.x + v.y + v.z + v.w;
        ob[j * 2 + 0] = __floats2bfloat162_rn(v.x, v.y);
        ob[j * 2 + 1] = __floats2bfloat162_rn(v.z, v.w);
    }
    red[t] = s;
    __syncthreads();
    for (int o = 128; o > 0; o >>= 1) {
        if (t < o) red[t] += red[t + o];
        __syncthreads();
    }
    if (t == 0) gXmean[row] = red[0] * (1.f / (float)HWPX);
}

// =====================================================================
// kprep: weights -> bf16 linear row-major images
// =====================================================================
__global__ __launch_bounds__(256) void kprep(const float* __restrict__ pw1_w,
                                             const float* __restrict__ pw_w)
{
    int i = blockIdx.x * 256 + threadIdx.x;
    if (i < 65536) {
        gA1[i] = __float2bfloat16(pw1_w[i]);
    } else {
        int j = i - 65536;            // 256 rows x 384 cols
        int m = j / 384, k = j % 384;
        gA2[j] = __float2bfloat16(pw_w[m * 768 + k]);
    }
}

// =====================================================================
// kgemm<KDIM, EP> (R8 config — best measured; do not touch):
// mma.sync bf16, CTA 256m x 128p, 8 warps (2x4), warp tile 128m x 32p.
// grid (128, 1, BATCH), 256 threads.
// =====================================================================
template<int KDIM, int EP>
__global__ __launch_bounds__(256, 1)
void kgemm(const __nv_bfloat16* __restrict__ Aimg,
           const __nv_bfloat16* __restrict__ Bsrc,
           const float* __restrict__ bias,
           const float* __restrict__ xres,
           float* __restrict__ out)
{
    constexpr int KC = 64;
    constexpr int NCHUNK = KDIM / KC;
    constexpr int ASZ = 256 * KDIM * 2;      // bytes (256 m-rows)
    constexpr int BROW = 256;                // bytes per B k-row (128 bf16)
    constexpr int BSZ = KC * BROW;           // 16KB per buffer

    extern __shared__ char sraw[];
    const uint32_t rawu = smem_u32(sraw);
    const uint32_t sbase = (rawu + 127u) & ~127u;
    const uint32_t uA = sbase;
    const uint32_t uB = sbase + ASZ;
    float* sg = (float*)(sraw + (sbase - rawu) + ASZ + 2 * BSZ);   // [4][256] (EP1)

    const int t = threadIdx.x, wid = t >> 5, lane = t & 31;
    const int b = blockIdx.z, pc = blockIdx.x;
    const int p0 = pc * 128;
    const int wm = (wid >> 2) * 128;         // warp m offset (0 or 128)
    const int wp = (wid & 3) * 32;           // warp p offset

    const char* Bb = (const char*)(Bsrc + (size_t)b * KDIM * HWPX);
    const char* Ab = (const char*)Aimg;

    // ---- A load (swizzled), full 256 x K ----
    {
        constexpr int CPR = KDIM / 8;        // 16B chunks per row
        for (int i = t; i < 256 * CPR; i += 256) {
            int m = i / CPR, j = i % CPR;
            cp16(uA + m * (KDIM * 2) + ((j * 16) ^ ((m & 7) << 4)),
                 Ab + (size_t)m * (KDIM * 2) + j * 16);
        }
    }
    // ---- B chunk loader ----
    auto loadB = [&](int buf, int kc0) {
        uint32_t dst = uB + buf * BSZ;
#pragma unroll
        for (int i = t; i < KC * 16; i += 256) {
            int k = i >> 4, j = i & 15;
            cp16(dst + k * BROW + ((j * 16) ^ ((k & 7) << 4)),
                 Bb + ((size_t)(kc0 + k) * HWPX + p0) * 2 + j * 16);
        }
    };
    loadB(0, 0);
    cp_commit();                 // group0: A + B0
    if (NCHUNK > 1) { loadB(1, KC); cp_commit(); }

    float acc[8][4][4];
#pragma unroll
    for (int mi = 0; mi < 8; mi++)
#pragma unroll
        for (int ni = 0; ni < 4; ni++)
#pragma unroll
            for (int r = 0; r < 4; r++) acc[mi][ni][r] = 0.f;

    const int a_m  = wm + (lane & 15);
    const int a_kb = (lane >> 4) * 16;
    const uint32_t aBase = uA + a_m * (KDIM * 2);
    const uint32_t aSwz  = (a_m & 7) << 4;
    const int b_k  = lane & 15;
    const int b_nb = wp * 2 + (lane >> 4) * 16;
    const uint32_t bSwzK = (b_k & 7) << 4;

    for (int c = 0; c < NCHUNK; c++) {
        // final chunk: drain fully (R4 race fix, protected).
        if (c == NCHUNK - 1) cp_wait<0>(); else cp_wait<1>();
        __syncthreads();
        const uint32_t bb = uB + (c & 1) * BSZ + b_k * BROW;
#pragma unroll
        for (int ks = 0; ks < KC / 16; ks++) {
            const int kB = ks * 32;
            uint32_t bf[2][4];
#pragma unroll
            for (int h = 0; h < 2; h++)
                ldsm_x4_t(bf[h], bb + ks * 16 * BROW + ((b_nb + h * 32) ^ bSwzK));
#pragma unroll
            for (int mi = 0; mi < 8; mi++) {
                uint32_t a[4];
                ldsm_x4(a, aBase + mi * 16 * (KDIM * 2) +
                           (((c * KC * 2) + kB + a_kb) ^ aSwz));
#pragma unroll
                for (int ni = 0; ni < 4; ni++)
                    mma16816(acc[mi][ni], a, &bf[ni >> 1][(ni & 1) * 2]);
            }
        }
        __syncthreads();
        if (c + 2 < NCHUNK) { loadB(c & 1, (c + 2) * KC); cp_commit(); }
    }

    // ---- epilogue ----
    const int erow = lane >> 2;
    const int ecol = (lane & 3) * 2;
    if (EP == 2) {
#pragma unroll
        for (int mi = 0; mi < 8; mi++) {
#pragma unroll
            for (int h = 0; h < 2; h++) {
                const int m = wm + mi * 16 + h * 8 + erow;
                const float bv = bias[m];
                const size_t rb = ((size_t)(b * OCH + m)) * HWPX + p0;
#pragma unroll
                for (int ni = 0; ni < 4; ni++) {
                    const size_t o = rb + wp + ni * 8 + ecol;
                    float2 xr = *(const float2*)&xres[o];
                    float2 v;
                    v.x = acc[mi][ni][2 * h]     + bv + xr.x;
                    v.y = acc[mi][ni][2 * h + 1] + bv + xr.y;
                    *(float2*)&out[o] = v;
                }
            }
        }
    } else {
        float rs[8][2];
#pragma unroll
        for (int mi = 0; mi < 8; mi++) {
#pragma unroll
            for (int h = 0; h < 2; h++) {
                const int m = wm + mi * 16 + h * 8 + erow;
                const float bv = bias[m];
                float s2 = 0.f;
#pragma unroll
                for (int ni = 0; ni < 4; ni++) {
                    float v0 = fmaxf(acc[mi][ni][2 * h]     + bv, 0.f);
                    float v1 = fmaxf(acc[mi][ni][2 * h + 1] + bv, 0.f);
                    s2 += v0 + v1;
                    if (m < KSEL) {
                        size_t o = ((size_t)(b * KSEL + m)) * HWPX + p0 + wp + ni * 8 + ecol;
                        *(__nv_bfloat162*)&g_selb[o] = __floats2bfloat162_rn(v0, v1);
                    }
                }
                rs[mi][h] = s2;
            }
        }
#pragma unroll
        for (int mi = 0; mi < 8; mi++)
#pragma unroll
            for (int h = 0; h < 2; h++) {
                rs[mi][h] += __shfl_xor_sync(0xffffffffu, rs[mi][h], 1);
                rs[mi][h] += __shfl_xor_sync(0xffffffffu, rs[mi][h], 2);
            }
        if ((lane & 3) == 0) {
#pragma unroll
            for (int mi = 0; mi < 8; mi++)
#pragma unroll
                for (int h = 0; h < 2; h++)
                    sg[(wid & 3) * 256 + wm + mi * 16 + h * 8 + erow] = rs[mi][h];
        }
        __syncthreads();
        g_gap2_part[(b * MCH + t) * 128 + pc] =
            sg[t] + sg[256 + t] + sg[512 + t] + sg[768 + t];
    }
}

// =====================================================================
// k2a: gap (exact, from xmean) + gap2 partial reduce. grid 288.
// =====================================================================
__global__ __launch_bounds__(256) void k2a(const float* __restrict__ pw1_w,
                                           const float* __restrict__ pw1_b)
{
    const int t = threadIdx.x, wid = t >> 5, lane = t & 31;
    if (blockIdx.x < 32) {
        __shared__ float sxm[2048];
        for (int i = t; i < 2048; i += 256) sxm[i] = gXmean[i];
        __syncthreads();
        const int m = blockIdx.x * 8 + wid;
        const float* wr = pw1_w + m * CIN;
        float acc[8] = {0.f, 0.f, 0.f, 0.f, 0.f, 0.f, 0.f, 0.f};
        for (int c = lane; c < CIN; c += 32) {
            float w = wr[c];
#pragma unroll
            for (int bb = 0; bb < 8; bb++) acc[bb] = fmaf(sxm[bb * 256 + c], w, acc[bb]);
        }
#pragma unroll
        for (int bb = 0; bb < 8; bb++) acc[bb] = wred(acc[bb]);
        if (lane == 0) {
            float bv = pw1_b[m];
#pragma unroll
            for (int bb = 0; bb < 8; bb++) g_gapv[bb * 256 + m] = acc[bb] + bv;
        }
    } else {
        const int rr = (blockIdx.x - 32) * 8 + wid;
        const float4* p4 = (const float4*)(g_gap2_part + (size_t)rr * 128);
        float4 v = p4[lane];
        float a = wred(v.x + v.y + v.z + v.w);
        if (lane == 0) g_gap2v[rr] = a * (1.f / (float)HWPX);
    }
}

// =====================================================================
// k2b: fc1 (512 outputs x 8 batches). grid 64, warp per j.
// =====================================================================
__global__ __launch_bounds__(256) void k2b(const float* __restrict__ fc1_w,
                                           const float* __restrict__ fc1_b)
{
    __shared__ float sgap[2048];
    const int t = threadIdx.x, wid = t >> 5, lane = t & 31;
    for (int i = t; i < 2048; i += 256) sgap[i] = g_gapv[i];
    __syncthreads();
    const int j = blockIdx.x * 8 + wid;
    const float* wr = fc1_w + j * MCH;
    float acc[8] = {0.f, 0.f, 0.f, 0.f, 0.f, 0.f, 0.f, 0.f};
    for (int c = lane; c < MCH; c += 32) {
        float w = wr[c];
#pragma unroll
        for (int bb = 0; bb < 8; bb++) acc[bb] = fmaf(sgap[bb * 256 + c], w, acc[bb]);
    }
#pragma unroll
    for (int bb = 0; bb < 8; bb++) acc[bb] = wred(acc[bb]);
    if (lane == 0) {
        float bv = fc1_b[j];
#pragma unroll
        for (int bb = 0; bb < 8; bb++) g_hidv[bb * 512 + j] = fmaxf(acc[bb] + bv, 0.f);
    }
}

// =====================================================================
// k2c: fc2 + sigmoid (256 outputs x 8 batches). grid 32, warp per j.
// =====================================================================
__global__ __launch_bounds__(256) void k2c(const float* __restrict__ fc2_w,
                                           const float* __restrict__ fc2_b)
{
    __shared__ float shid[4096];
    const int t = threadIdx.x, wid = t >> 5, lane = t & 31;
    for (int i = t; i < 4096; i += 256) shid[i] = g_hidv[i];
    __syncthreads();
    const int j = blockIdx.x * 8 + wid;
    const float* wr = fc2_w + j * 512;
    float acc[8] = {0.f, 0.f, 0.f, 0.f, 0.f, 0.f, 0.f, 0.f};
    for (int c = lane; c < 512; c += 32) {
        float w = wr[c];
#pragma unroll
        for (int bb = 0; bb < 8; bb++) acc[bb] = fmaf(shid[bb * 512 + c], w, acc[bb]);
    }
#pragma unroll
    for (int bb = 0; bb < 8; bb++) acc[bb] = wred(acc[bb]);
    if (lane == 0) {
        float bv = fc2_b[j];
#pragma unroll
        for (int bb = 0; bb < 8; bb++)
            g_scorev[bb * 256 + j] = 1.f / (1.f + expf(-(acc[bb] + bv)));
    }
}

// =====================================================================
// k2d: top-k mask + offsets + effective depthwise weights + mask export.
// grid 64 = 8 batches x 8 slices.
// =====================================================================
__global__ __launch_bounds__(256) void k2d(const float* __restrict__ off_w,
                                           const float* __restrict__ off_b,
                                           const float* __restrict__ dw3,
                                           const float* __restrict__ dw5,
                                           const float* __restrict__ dw7)
{
    __shared__ float ssc[256], sg2[256], smask[128], sscl[3], ssht[3];
    const int t = threadIdx.x, wid = t >> 5, lane = t & 31;
    const int bb = blockIdx.x >> 3, slice = blockIdx.x & 7;

    ssc[t] = g_scorev[bb * 256 + t];
    sg2[t] = g_gap2v[bb * 256 + t];
    __syncthreads();

    if (wid < 6) {
        const int r = wid;
        const float* wr = off_w + r * MCH;
        float a = 0.f;
        for (int c = lane; c < MCH; c += 32) a = fmaf(sg2[c], wr[c], a);
        a = wred(a);
        if (lane == 0) {
            float o = tanhf(a + off_b[r]);
            if ((r & 1) == 0) sscl[r >> 1] = 1.f / (1.f + expf(-o));
            else              ssht[r >> 1] = tanhf(o);
        }
    }
    if (t < KSEL) {
        float sc = ssc[t];
        int cnt = 0;
        for (int j = 0; j < MCH; j++) {
            float sj = ssc[j];
            cnt += (sj > sc) || (sj == sc && j < t);
        }
        float mk = (cnt < KSEL) ? 1.f : 0.f;
        smask[t] = mk;
        if (slice == 0) g_maskv[bb * KSEL + t] = mk;   // export for k3 skip
    }
    __syncthreads();

    for (int i = slice * 256 + t; i < 1152; i += 2048) {
        int c = i / 9;
        g_w3[bb * 1152 + i] = fmaf(dw3[i], 1.f + sscl[0], ssht[0]) * smask[c];
    }
    for (int i = slice * 256 + t; i < 3200; i += 2048) {
        int c = i / 25;
        g_w5[bb * 3200 + i] = fmaf(dw5[i], 1.f + sscl[1], ssht[1]) * smask[c];
    }
    for (int i = slice * 256 + t; i < 6272; i += 2048) {
        int c = i / 49;
        g_w7[bb * 6272 + i] = fmaf(dw7[i], 1.f + sscl[2], ssht[2]) * smask[c];
    }
}

// =====================================================================
// k3 (R12): R8 scalar dwconv + masked-channel fast path.
// Inactive (masked-out) channels have all-zero weights -> conv == 0.0
// exactly; write zeros directly and skip staging + 332 FMAs.
// Bit-identical to computing with zero weights.
// =====================================================================
__global__ __launch_bounds__(256) void k3_dwconv()
{
    __shared__ float s[38][40];
    __shared__ float sw[84];

    const int b = blockIdx.z;
    const int c = blockIdx.y;
    const int tile = blockIdx.x;
    const int ty0 = (tile >> 2) * 32;
    const int tx0 = (tile & 3) * 32;
    const int t = threadIdx.x;

    const int py  = t >> 3;          // 0..31
    const int px0 = (t & 7) * 4;     // 0,4,...,28
    const size_t obase = ((size_t)(b * (3 * KSEL) + c)) * HWPX + (size_t)(ty0 + py) * WW + tx0 + px0;

    // masked-out channel: conv output is exactly zero
    if (g_maskv[b * KSEL + c] == 0.f) {
        const uint2 z = make_uint2(0u, 0u);
        *(uint2*)&g_fusedb[obase]                          = z;
        *(uint2*)&g_fusedb[obase + (size_t)KSEL * HWPX]    = z;
        *(uint2*)&g_fusedb[obase + (size_t)2 * KSEL * HWPX] = z;
        return;
    }

    const __nv_bfloat16* in = g_selb + ((size_t)(b * KSEL + c)) * HWPX;

    for (int i = t; i < 38 * 38; i += 256) {
        int r = i / 38, cc = i % 38;
        int gy = ty0 + r - 3, gx = tx0 + cc - 3;
        s[r][cc] = (gy >= 0 && gy < HH && gx >= 0 && gx < WW) ? __bfloat162float(in[gy * WW + gx]) : 0.f;
    }
    if (t < 9)        sw[t] = g_w3[(b * KSEL + c) * 9 + t];
    else if (t < 34)  sw[t] = g_w5[(b * KSEL + c) * 25 + (t - 9)];
    else if (t < 83)  sw[t] = g_w7[(b * KSEL + c) * 49 + (t - 34)];
    __syncthreads();

    float a3[4] = {0.f, 0.f, 0.f, 0.f};
    float a5[4] = {0.f, 0.f, 0.f, 0.f};
    float a7[4] = {0.f, 0.f, 0.f, 0.f};

#pragma unroll
    for (int dy = 0; dy < 7; dy++) {
        const float* row = &s[py + dy][0];
        float4 v0 = *(const float4*)&row[px0];
        float4 v1 = *(const float4*)&row[px0 + 4];
        float4 v2 = *(const float4*)&row[px0 + 8];
        float w[12] = {v0.x, v0.y, v0.z, v0.w, v1.x, v1.y, v1.z, v1.w,
                       v2.x, v2.y, v2.z, v2.w};
#pragma unroll
        for (int dx = 0; dx < 7; dx++) {
            float wt = sw[34 + dy * 7 + dx];
#pragma unroll
            for (int j = 0; j < 4; j++) a7[j] = fmaf(w[j + dx], wt, a7[j]);
        }
        if (dy >= 1 && dy <= 5) {
#pragma unroll
            for (int dx = 0; dx < 5; dx++) {
                float wt = sw[9 + (dy - 1) * 5 + dx];
#pragma unroll
                for (int j = 0; j < 4; j++) a5[j] = fmaf(w[j + 1 + dx], wt, a5[j]);
            }
        }
        if (dy >= 2 && dy <= 4) {
#pragma unroll
            for (int dx = 0; dx < 3; dx++) {
                float wt = sw[(dy - 2) * 3 + dx];
#pragma unroll
                for (int j = 0; j < 4; j++) a3[j] = fmaf(w[j + 2 + dx], wt, a3[j]);
            }
        }
    }

    {
        __nv_bfloat162 p0 = __floats2bfloat162_rn(a3[0], a3[1]);
        __nv_bfloat162 p1 = __floats2bfloat162_rn(a3[2], a3[3]);
        *(uint2*)&g_fusedb[obase] = make_uint2(*(uint32_t*)&p0, *(uint32_t*)&p1);
        p0 = __floats2bfloat162_rn(a5[0], a5[1]);
        p1 = __floats2bfloat162_rn(a5[2], a5[3]);
        *(uint2*)&g_fusedb[obase + (size_t)KSEL * HWPX] = make_uint2(*(uint32_t*)&p0, *(uint32_t*)&p1);
        p0 = __floats2bfloat162_rn(a7[0], a7[1]);
        p1 = __floats2bfloat162_rn(a7[2], a7[3]);
        *(uint2*)&g_fusedb[obase + (size_t)2 * KSEL * HWPX] = make_uint2(*(uint32_t*)&p0, *(uint32_t*)&p1);
    }
}

// =====================================================================
extern "C" void kernel_launch(void* const* d_in, const int* in_sizes, int n_in,
                              void* d_out, int out_size)
{
    const float* x     = (const float*)d_in[0];
    const float* pw1_w = (const float*)d_in[1];
    const float* pw1_b = (const float*)d_in[2];
    const float* fc1_w = (const float*)d_in[3];
    const float* fc1_b = (const float*)d_in[4];
    const float* fc2_w = (const float*)d_in[5];
    const float* fc2_b = (const float*)d_in[6];
    const float* off_w = (const float*)d_in[7];
    const float* off_b = (const float*)d_in[8];
    const float* dw3   = (const float*)d_in[9];
    const float* dw5   = (const float*)d_in[10];
    const float* dw7   = (const float*)d_in[11];
    const float* pw_w  = (const float*)d_in[12];
    const float* pw_b  = (const float*)d_in[13];
    float* out = (float*)d_out;

    const int smem1 = 256 * 256 * 2 + 2 * 16384 + 4 * 256 * 4 + 256;   // 168192
    const int smem2 = 256 * 384 * 2 + 2 * 16384 + 256;                  // 229632
    cudaFuncSetAttribute((const void*)kgemm<256, 1>, cudaFuncAttributeMaxDynamicSharedMemorySize, smem1);
    cudaFuncSetAttribute((const void*)kgemm<384, 2>, cudaFuncAttributeMaxDynamicSharedMemorySize, smem2);

    __nv_bfloat16 *gA1p, *gA2p, *gXbp, *gFbp;
    cudaGetSymbolAddress((void**)&gA1p, gA1);
    cudaGetSymbolAddress((void**)&gA2p, gA2);
    cudaGetSymbolAddress((void**)&gXbp, gXb);
    cudaGetSymbolAddress((void**)&gFbp, g_fusedb);

    kxc<<<BATCH * CIN, 256>>>(x);
    kprep<<<640, 256>>>(pw1_w, pw_w);
    kgemm<256, 1><<<dim3(128, 1, BATCH), 256, smem1>>>(gA1p, gXbp, pw1_b, nullptr, nullptr);
    k2a<<<288, 256>>>(pw1_w, pw1_b);
    k2b<<<64, 256>>>(fc1_w, fc1_b);
    k2c<<<32, 256>>>(fc2_w, fc2_b);
    k2d<<<64, 256>>>(off_w, off_b, dw3, dw5, dw7);
    k3_dwconv<<<dim3(16, KSEL, BATCH), 256>>>();
    kgemm<384, 2><<<dim3(128, 1, BATCH), 256, smem2>>>(gA2p, gFbp, pw_b, x, out);
}

// round 13
// speedup vs baseline: 1.7414x; 1.0544x over previous
#include <cuda_runtime.h>
#include <cuda_bf16.h>
#include <cstdint>
#include <math.h>

#define BATCH 8
#define CIN   256
#define MCH   256
#define OCH   256
#define HH    128
#define WW    128
#define HWPX  16384
#define KSEL  128

// ---------------- device scratch ----------------
__device__ __align__(128) __nv_bfloat16 gXb[(size_t)BATCH * CIN * HWPX];           // x bf16
__device__ __align__(128) __nv_bfloat16 g_selb[(size_t)BATCH * KSEL * HWPX];       // relu(h)[:,:128] bf16
__device__ __align__(128) __nv_bfloat16 g_fusedb[(size_t)BATCH * 3 * KSEL * HWPX]; // dwconv out bf16
__device__ __align__(128) __nv_bfloat16 gA1[256 * 256];                            // pw1_w bf16 linear
__device__ __align__(128) __nv_bfloat16 gA2b[(size_t)BATCH * 256 * 384];           // per-batch GATHERED pw_w bf16
__device__ float gXmean[BATCH * CIN];
__device__ float g_gap2_part[BATCH * MCH * 128];
__device__ float g_gapv[BATCH * MCH];
__device__ float g_gap2v[BATCH * MCH];
__device__ float g_hidv[BATCH * 512];
__device__ float g_scorev[BATCH * MCH];
__device__ float g_maskv[BATCH * KSEL];
__device__ int   g_rowsrc[BATCH * 384];    // gathered K row sources into fused (flat 0..383)
__device__ int   g_kp[BATCH];              // padded K' per batch (multiple of 64)
__device__ int   g_padch[BATCH];           // designated zero pad channel (-1 if none)
__device__ float g_w3[BATCH * KSEL * 9];
__device__ float g_w5[BATCH * KSEL * 25];
__device__ float g_w7[BATCH * KSEL * 49];

// ---------------- PTX helpers (baseline compute_103 features only) ----------------
__device__ __forceinline__ uint32_t smem_u32(const void* p) {
    uint32_t a;
    asm("{ .reg .u64 t; cvta.to.shared.u64 t, %1; cvt.u32.u64 %0, t; }" : "=r"(a) : "l"(p));
    return a;
}
__device__ __forceinline__ void cp16(uint32_t dst, const void* src) {
    asm volatile("cp.async.cg.shared.global [%0], [%1], 16;" :: "r"(dst), "l"(src) : "memory");
}
__device__ __forceinline__ void cp_commit() { asm volatile("cp.async.commit_group;" ::: "memory"); }
template<int N> __device__ __forceinline__ void cp_wait() { asm volatile("cp.async.wait_group %0;" :: "n"(N) : "memory"); }

__device__ __forceinline__ void ldsm_x4(uint32_t* r, uint32_t addr) {
    asm volatile("ldmatrix.sync.aligned.m8n8.x4.shared.b16 {%0,%1,%2,%3}, [%4];"
                 : "=r"(r[0]), "=r"(r[1]), "=r"(r[2]), "=r"(r[3]) : "r"(addr));
}
__device__ __forceinline__ void ldsm_x4_t(uint32_t* r, uint32_t addr) {
    asm volatile("ldmatrix.sync.aligned.m8n8.x4.trans.shared.b16 {%0,%1,%2,%3}, [%4];"
                 : "=r"(r[0]), "=r"(r[1]), "=r"(r[2]), "=r"(r[3]) : "r"(addr));
}
__device__ __forceinline__ void mma16816(float* d, const uint32_t* a, const uint32_t* b) {
    asm volatile("mma.sync.aligned.m16n8k16.row.col.f32.bf16.bf16.f32 "
                 "{%0,%1,%2,%3}, {%4,%5,%6,%7}, {%8,%9}, {%0,%1,%2,%3};"
                 : "+f"(d[0]), "+f"(d[1]), "+f"(d[2]), "+f"(d[3])
                 : "r"(a[0]), "r"(a[1]), "r"(a[2]), "r"(a[3]), "r"(b[0]), "r"(b[1]));
}
__device__ __forceinline__ float wred(float v) {
    v += __shfl_xor_sync(0xffffffffu, v, 16);
    v += __shfl_xor_sync(0xffffffffu, v, 8);
    v += __shfl_xor_sync(0xffffffffu, v, 4);
    v += __shfl_xor_sync(0xffffffffu, v, 2);
    v += __shfl_xor_sync(0xffffffffu, v, 1);
    return v;
}

// =====================================================================
// kxc: x fp32 -> bf16 + exact fp32 row means (score path stays exact)
// =====================================================================
__global__ __launch_bounds__(256) void kxc(const float* __restrict__ x)
{
    __shared__ float red[256];
    const int row = blockIdx.x;
    const int t = threadIdx.x;
    const float4* in4 = (const float4*)(x + (size_t)row * HWPX);
    __nv_bfloat162* ob = (__nv_bfloat162*)(gXb + (size_t)row * HWPX);
    float s = 0.f;
#pragma unroll
    for (int it = 0; it < 16; it++) {
        int j = t + it * 256;
        float4 v = in4[j];
        s += v.x + v.y + v.z + v.w;
        ob[j * 2 + 0] = __floats2bfloat162_rn(v.x, v.y);
        ob[j * 2 + 1] = __floats2bfloat162_rn(v.z, v.w);
    }
    red[t] = s;
    __syncthreads();
    for (int o = 128; o > 0; o >>= 1) {
        if (t < o) red[t] += red[t + o];
        __syncthreads();
    }
    if (t == 0) gXmean[row] = red[0] * (1.f / (float)HWPX);
}

// =====================================================================
// kprep: pw1_w -> bf16 linear (gA1 only; gemm2's A is gathered later)
// =====================================================================
__global__ __launch_bounds__(256) void kprep(const float* __restrict__ pw1_w)
{
    int i = blockIdx.x * 256 + threadIdx.x;
    gA1[i] = __float2bfloat16(pw1_w[i]);
}

// =====================================================================
// kgemm<KDIM, EP=1> (R8 config, dense; GEMM1 only — do not touch):
// grid (128, 1, BATCH), 256 threads.
// =====================================================================
template<int KDIM, int EP>
__global__ __launch_bounds__(256, 1)
void kgemm(const __nv_bfloat16* __restrict__ Aimg,
           const __nv_bfloat16* __restrict__ Bsrc,
           const float* __restrict__ bias,
           const float* __restrict__ xres,
           float* __restrict__ out)
{
    constexpr int KC = 64;
    constexpr int NCHUNK = KDIM / KC;
    constexpr int ASZ = 256 * KDIM * 2;
    constexpr int BROW = 256;
    constexpr int BSZ = KC * BROW;

    extern __shared__ char sraw[];
    const uint32_t rawu = smem_u32(sraw);
    const uint32_t sbase = (rawu + 127u) & ~127u;
    const uint32_t uA = sbase;
    const uint32_t uB = sbase + ASZ;
    float* sg = (float*)(sraw + (sbase - rawu) + ASZ + 2 * BSZ);

    const int t = threadIdx.x, wid = t >> 5, lane = t & 31;
    const int b = blockIdx.z, pc = blockIdx.x;
    const int p0 = pc * 128;
    const int wm = (wid >> 2) * 128;
    const int wp = (wid & 3) * 32;

    const char* Bb = (const char*)(Bsrc + (size_t)b * KDIM * HWPX);
    const char* Ab = (const char*)Aimg;

    {
        constexpr int CPR = KDIM / 8;
        for (int i = t; i < 256 * CPR; i += 256) {
            int m = i / CPR, j = i % CPR;
            cp16(uA + m * (KDIM * 2) + ((j * 16) ^ ((m & 7) << 4)),
                 Ab + (size_t)m * (KDIM * 2) + j * 16);
        }
    }
    auto loadB = [&](int buf, int kc0) {
        uint32_t dst = uB + buf * BSZ;
#pragma unroll
        for (int i = t; i < KC * 16; i += 256) {
            int k = i >> 4, j = i & 15;
            cp16(dst + k * BROW + ((j * 16) ^ ((k & 7) << 4)),
                 Bb + ((size_t)(kc0 + k) * HWPX + p0) * 2 + j * 16);
        }
    };
    loadB(0, 0);
    cp_commit();
    if (NCHUNK > 1) { loadB(1, KC); cp_commit(); }

    float acc[8][4][4];
#pragma unroll
    for (int mi = 0; mi < 8; mi++)
#pragma unroll
        for (int ni = 0; ni < 4; ni++)
#pragma unroll
            for (int r = 0; r < 4; r++) acc[mi][ni][r] = 0.f;

    const int a_m  = wm + (lane & 15);
    const int a_kb = (lane >> 4) * 16;
    const uint32_t aBase = uA + a_m * (KDIM * 2);
    const uint32_t aSwz  = (a_m & 7) << 4;
    const int b_k  = lane & 15;
    const int b_nb = wp * 2 + (lane >> 4) * 16;
    const uint32_t bSwzK = (b_k & 7) << 4;

    for (int c = 0; c < NCHUNK; c++) {
        if (c == NCHUNK - 1) cp_wait<0>(); else cp_wait<1>();   // R4 race fix
        __syncthreads();
        const uint32_t bb = uB + (c & 1) * BSZ + b_k * BROW;
#pragma unroll
        for (int ks = 0; ks < KC / 16; ks++) {
            const int kB = ks * 32;
            uint32_t bf[2][4];
#pragma unroll
            for (int h = 0; h < 2; h++)
                ldsm_x4_t(bf[h], bb + ks * 16 * BROW + ((b_nb + h * 32) ^ bSwzK));
#pragma unroll
            for (int mi = 0; mi < 8; mi++) {
                uint32_t a[4];
                ldsm_x4(a, aBase + mi * 16 * (KDIM * 2) +
                           (((c * KC * 2) + kB + a_kb) ^ aSwz));
#pragma unroll
                for (int ni = 0; ni < 4; ni++)
                    mma16816(acc[mi][ni], a, &bf[ni >> 1][(ni & 1) * 2]);
            }
        }
        __syncthreads();
        if (c + 2 < NCHUNK) { loadB(c & 1, (c + 2) * KC); cp_commit(); }
    }

    const int erow = lane >> 2;
    const int ecol = (lane & 3) * 2;
    {
        float rs[8][2];
#pragma unroll
        for (int mi = 0; mi < 8; mi++) {
#pragma unroll
            for (int h = 0; h < 2; h++) {
                const int m = wm + mi * 16 + h * 8 + erow;
                const float bv = bias[m];
                float s2 = 0.f;
#pragma unroll
                for (int ni = 0; ni < 4; ni++) {
                    float v0 = fmaxf(acc[mi][ni][2 * h]     + bv, 0.f);
                    float v1 = fmaxf(acc[mi][ni][2 * h + 1] + bv, 0.f);
                    s2 += v0 + v1;
                    if (m < KSEL) {
                        size_t o = ((size_t)(b * KSEL + m)) * HWPX + p0 + wp + ni * 8 + ecol;
                        *(__nv_bfloat162*)&g_selb[o] = __floats2bfloat162_rn(v0, v1);
                    }
                }
                rs[mi][h] = s2;
            }
        }
#pragma unroll
        for (int mi = 0; mi < 8; mi++)
#pragma unroll
            for (int h = 0; h < 2; h++) {
                rs[mi][h] += __shfl_xor_sync(0xffffffffu, rs[mi][h], 1);
                rs[mi][h] += __shfl_xor_sync(0xffffffffu, rs[mi][h], 2);
            }
        if ((lane & 3) == 0) {
#pragma unroll
            for (int mi = 0; mi < 8; mi++)
#pragma unroll
                for (int h = 0; h < 2; h++)
                    sg[(wid & 3) * 256 + wm + mi * 16 + h * 8 + erow] = rs[mi][h];
        }
        __syncthreads();
        g_gap2_part[(b * MCH + t) * 128 + pc] =
            sg[t] + sg[256 + t] + sg[512 + t] + sg[768 + t];
    }
}

// =====================================================================
// kgemm2s (R13): sparse-K GEMM2. K' = g_kp[b] (<=384, multiple of 64),
// B rows gathered via g_rowsrc (zero rows of fused skipped), A gathered
// per batch into gA2b by kprep2. grid (128, 1, BATCH), 256 threads.
// =====================================================================
__global__ __launch_bounds__(256, 1)
void kgemm2s(const float* __restrict__ bias,
             const float* __restrict__ xres,
             float* __restrict__ out)
{
    constexpr int KC = 64;
    constexpr int ASZmax = 256 * 384 * 2;
    constexpr int BROW = 256;
    constexpr int BSZ = KC * BROW;

    extern __shared__ char sraw[];
    const uint32_t rawu = smem_u32(sraw);
    const uint32_t sbase = (rawu + 127u) & ~127u;
    const uint32_t uA = sbase;
    const uint32_t uB = sbase + ASZmax;

    const int t = threadIdx.x, wid = t >> 5, lane = t & 31;
    const int b = blockIdx.z, pc = blockIdx.x;
    const int p0 = pc * 128;
    const int wm = (wid >> 2) * 128;
    const int wp = (wid & 3) * 32;

    const int kp = g_kp[b];
    const int nchunk = kp >> 6;
    const int* rs = g_rowsrc + b * 384;
    const char* Bb = (const char*)(g_fusedb + (size_t)b * 384 * HWPX);
    const char* Ab = (const char*)(gA2b + (size_t)b * 256 * 384);
    const int kp2 = kp * 2;               // A row stride in bytes

    // ---- A load (swizzled), 256 x kp ----
    {
        const int cpr = kp >> 3;          // 16B chunks per row
        for (int i = t; i < 256 * cpr; i += 256) {
            int m = i / cpr, j = i % cpr;
            cp16(uA + m * kp2 + ((j * 16) ^ ((m & 7) << 4)),
                 Ab + (size_t)m * kp2 + j * 16);
        }
    }
    // ---- B chunk loader (row-gathered) ----
    auto loadB = [&](int buf, int kc0) {
        uint32_t dst = uB + buf * BSZ;
#pragma unroll
        for (int i = t; i < KC * 16; i += 256) {
            int k = i >> 4, j = i & 15;
            int row = rs[kc0 + k];
            cp16(dst + k * BROW + ((j * 16) ^ ((k & 7) << 4)),
                 Bb + ((size_t)row * HWPX + p0) * 2 + j * 16);
        }
    };
    loadB(0, 0);
    cp_commit();
    if (nchunk > 1) { loadB(1, KC); cp_commit(); }

    float acc[8][4][4];
#pragma unroll
    for (int mi = 0; mi < 8; mi++)
#pragma unroll
        for (int ni = 0; ni < 4; ni++)
#pragma unroll
            for (int r = 0; r < 4; r++) acc[mi][ni][r] = 0.f;

    const int a_m  = wm + (lane & 15);
    const int a_kb = (lane >> 4) * 16;
    const uint32_t aBase = uA + a_m * kp2;
    const uint32_t aSwz  = (a_m & 7) << 4;
    const int b_k  = lane & 15;
    const int b_nb = wp * 2 + (lane >> 4) * 16;
    const uint32_t bSwzK = (b_k & 7) << 4;

    for (int c = 0; c < nchunk; c++) {
        if (c == nchunk - 1) cp_wait<0>(); else cp_wait<1>();   // R4 race fix
        __syncthreads();
        const uint32_t bb = uB + (c & 1) * BSZ + b_k * BROW;
#pragma unroll
        for (int ks = 0; ks < KC / 16; ks++) {
            const int kB = ks * 32;
            uint32_t bf[2][4];
#pragma unroll
            for (int h = 0; h < 2; h++)
                ldsm_x4_t(bf[h], bb + ks * 16 * BROW + ((b_nb + h * 32) ^ bSwzK));
#pragma unroll
            for (int mi = 0; mi < 8; mi++) {
                uint32_t a[4];
                ldsm_x4(a, aBase + mi * 16 * kp2 +
                           (((c * KC * 2) + kB + a_kb) ^ aSwz));
#pragma unroll
                for (int ni = 0; ni < 4; ni++)
                    mma16816(acc[mi][ni], a, &bf[ni >> 1][(ni & 1) * 2]);
            }
        }
        __syncthreads();
        if (c + 2 < nchunk) { loadB(c & 1, (c + 2) * KC); cp_commit(); }
    }

    // ---- epilogue: +bias +residual, fp32 out ----
    const int erow = lane >> 2;
    const int ecol = (lane & 3) * 2;
#pragma unroll
    for (int mi = 0; mi < 8; mi++) {
#pragma unroll
        for (int h = 0; h < 2; h++) {
            const int m = wm + mi * 16 + h * 8 + erow;
            const float bv = bias[m];
            const size_t rb = ((size_t)(b * OCH + m)) * HWPX + p0;
#pragma unroll
            for (int ni = 0; ni < 4; ni++) {
                const size_t o = rb + wp + ni * 8 + ecol;
                float2 xr = *(const float2*)&xres[o];
                float2 v;
                v.x = acc[mi][ni][2 * h]     + bv + xr.x;
                v.y = acc[mi][ni][2 * h + 1] + bv + xr.y;
                *(float2*)&out[o] = v;
            }
        }
    }
}

// =====================================================================
// k2a: gap (exact, from xmean) + gap2 partial reduce. grid 288.
// =====================================================================
__global__ __launch_bounds__(256) void k2a(const float* __restrict__ pw1_w,
                                           const float* __restrict__ pw1_b)
{
    const int t = threadIdx.x, wid = t >> 5, lane = t & 31;
    if (blockIdx.x < 32) {
        __shared__ float sxm[2048];
        for (int i = t; i < 2048; i += 256) sxm[i] = gXmean[i];
        __syncthreads();
        const int m = blockIdx.x * 8 + wid;
        const float* wr = pw1_w + m * CIN;
        float acc[8] = {0.f, 0.f, 0.f, 0.f, 0.f, 0.f, 0.f, 0.f};
        for (int c = lane; c < CIN; c += 32) {
            float w = wr[c];
#pragma unroll
            for (int bb = 0; bb < 8; bb++) acc[bb] = fmaf(sxm[bb * 256 + c], w, acc[bb]);
        }
#pragma unroll
        for (int bb = 0; bb < 8; bb++) acc[bb] = wred(acc[bb]);
        if (lane == 0) {
            float bv = pw1_b[m];
#pragma unroll
            for (int bb = 0; bb < 8; bb++) g_gapv[bb * 256 + m] = acc[bb] + bv;
        }
    } else {
        const int rr = (blockIdx.x - 32) * 8 + wid;
        const float4* p4 = (const float4*)(g_gap2_part + (size_t)rr * 128);
        float4 v = p4[lane];
        float a = wred(v.x + v.y + v.z + v.w);
        if (lane == 0) g_gap2v[rr] = a * (1.f / (float)HWPX);
    }
}

// =====================================================================
// k2b: fc1 (512 outputs x 8 batches). grid 64, warp per j.
// =====================================================================
__global__ __launch_bounds__(256) void k2b(const float* __restrict__ fc1_w,
                                           const float* __restrict__ fc1_b)
{
    __shared__ float sgap[2048];
    const int t = threadIdx.x, wid = t >> 5, lane = t & 31;
    for (int i = t; i < 2048; i += 256) sgap[i] = g_gapv[i];
    __syncthreads();
    const int j = blockIdx.x * 8 + wid;
    const float* wr = fc1_w + j * MCH;
    float acc[8] = {0.f, 0.f, 0.f, 0.f, 0.f, 0.f, 0.f, 0.f};
    for (int c = lane; c < MCH; c += 32) {
        float w = wr[c];
#pragma unroll
        for (int bb = 0; bb < 8; bb++) acc[bb] = fmaf(sgap[bb * 256 + c], w, acc[bb]);
    }
#pragma unroll
    for (int bb = 0; bb < 8; bb++) acc[bb] = wred(acc[bb]);
    if (lane == 0) {
        float bv = fc1_b[j];
#pragma unroll
        for (int bb = 0; bb < 8; bb++) g_hidv[bb * 512 + j] = fmaxf(acc[bb] + bv, 0.f);
    }
}

// =====================================================================
// k2c: fc2 + sigmoid (256 outputs x 8 batches). grid 32, warp per j.
// =====================================================================
__global__ __launch_bounds__(256) void k2c(const float* __restrict__ fc2_w,
                                           const float* __restrict__ fc2_b)
{
    __shared__ float shid[4096];
    const int t = threadIdx.x, wid = t >> 5, lane = t & 31;
    for (int i = t; i < 4096; i += 256) shid[i] = g_hidv[i];
    __syncthreads();
    const int j = blockIdx.x * 8 + wid;
    const float* wr = fc2_w + j * 512;
    float acc[8] = {0.f, 0.f, 0.f, 0.f, 0.f, 0.f, 0.f, 0.f};
    for (int c = lane; c < 512; c += 32) {
        float w = wr[c];
#pragma unroll
        for (int bb = 0; bb < 8; bb++) acc[bb] = fmaf(shid[bb * 512 + c], w, acc[bb]);
    }
#pragma unroll
    for (int bb = 0; bb < 8; bb++) acc[bb] = wred(acc[bb]);
    if (lane == 0) {
        float bv = fc2_b[j];
#pragma unroll
        for (int bb = 0; bb < 8; bb++)
            g_scorev[bb * 256 + j] = 1.f / (1.f + expf(-(acc[bb] + bv)));
    }
}

// =====================================================================
// k2d: top-k mask + offsets + effective dw weights + sparsity metadata.
// grid 64 = 8 batches x 8 slices.
// =====================================================================
__global__ __launch_bounds__(256) void k2d(const float* __restrict__ off_w,
                                           const float* __restrict__ off_b,
                                           const float* __restrict__ dw3,
                                           const float* __restrict__ dw5,
                                           const float* __restrict__ dw7)
{
    __shared__ float ssc[256], sg2[256], smask[128], sscl[3], ssht[3];
    const int t = threadIdx.x, wid = t >> 5, lane = t & 31;
    const int bb = blockIdx.x >> 3, slice = blockIdx.x & 7;

    ssc[t] = g_scorev[bb * 256 + t];
    sg2[t] = g_gap2v[bb * 256 + t];
    __syncthreads();

    if (wid < 6) {
        const int r = wid;
        const float* wr = off_w + r * MCH;
        float a = 0.f;
        for (int c = lane; c < MCH; c += 32) a = fmaf(sg2[c], wr[c], a);
        a = wred(a);
        if (lane == 0) {
            float o = tanhf(a + off_b[r]);
            if ((r & 1) == 0) sscl[r >> 1] = 1.f / (1.f + expf(-o));
            else              ssht[r >> 1] = tanhf(o);
        }
    }
    if (t < KSEL) {
        float sc = ssc[t];
        int cnt = 0;
        for (int j = 0; j < MCH; j++) {
            float sj = ssc[j];
            cnt += (sj > sc) || (sj == sc && j < t);
        }
        float mk = (cnt < KSEL) ? 1.f : 0.f;
        smask[t] = mk;
        if (slice == 0) g_maskv[bb * KSEL + t] = mk;
    }
    __syncthreads();

    // sparsity metadata (slice 0 only): active list, pads, kp, padch
    if (slice == 0 && t < 128) {
        int pos = 0, katot = 0, padc = -1;
        for (int j = 0; j < 128; j++) {
            int a = (smask[j] > 0.f);
            katot += a;
            if (j < t) pos += a;
            if (!a && padc < 0) padc = j;
        }
        if (smask[t] > 0.f) {
#pragma unroll
            for (int g = 0; g < 3; g++)
                g_rowsrc[bb * 384 + g * katot + pos] = g * 128 + t;
        }
        int kp = ((3 * katot + 63) >> 6) << 6;
        if (kp == 0) kp = 64;
        int npad = kp - 3 * katot;
        if (t < npad) g_rowsrc[bb * 384 + 3 * katot + t] = (padc >= 0 ? padc : 0);
        if (t == 0) { g_kp[bb] = kp; g_padch[bb] = padc; }
    }

    for (int i = slice * 256 + t; i < 1152; i += 2048) {
        int c = i / 9;
        g_w3[bb * 1152 + i] = fmaf(dw3[i], 1.f + sscl[0], ssht[0]) * smask[c];
    }
    for (int i = slice * 256 + t; i < 3200; i += 2048) {
        int c = i / 25;
        g_w5[bb * 3200 + i] = fmaf(dw5[i], 1.f + sscl[1], ssht[1]) * smask[c];
    }
    for (int i = slice * 256 + t; i < 6272; i += 2048) {
        int c = i / 49;
        g_w7[bb * 6272 + i] = fmaf(dw7[i], 1.f + sscl[2], ssht[2]) * smask[c];
    }
}

// =====================================================================
// kprep2: per-batch gathered A' for sparse GEMM2.
// A'[b][m][kk] = bf16(pw_w[m*768 + rowsrc[kk]]), row stride = kp (compact).
// grid (256, 8), 256 threads.
// =====================================================================
__global__ __launch_bounds__(256) void kprep2(const float* __restrict__ pw_w)
{
    const int m = blockIdx.x, b = blockIdx.y;
    const int kp = g_kp[b];
    const int* rs = g_rowsrc + b * 384;
    __nv_bfloat16* dst = gA2b + (size_t)b * 256 * 384 + (size_t)m * kp;
    const float* src = pw_w + (size_t)m * 768;
    for (int kk = threadIdx.x; kk < kp; kk += 256)
        dst[kk] = __float2bfloat16(src[rs[kk]]);
}

// =====================================================================
// k3 (R12 + R13): scalar dwconv, masked-channel skip.
// Inactive channels: no output needed (GEMM2 never reads them), EXCEPT
// the designated pad channel's plane-0 row, which must be zero.
// =====================================================================
__global__ __launch_bounds__(256) void k3_dwconv()
{
    __shared__ float s[38][40];
    __shared__ float sw[84];

    const int b = blockIdx.z;
    const int c = blockIdx.y;
    const int tile = blockIdx.x;
    const int ty0 = (tile >> 2) * 32;
    const int tx0 = (tile & 3) * 32;
    const int t = threadIdx.x;

    const int py  = t >> 3;
    const int px0 = (t & 7) * 4;
    const size_t obase = ((size_t)(b * (3 * KSEL) + c)) * HWPX + (size_t)(ty0 + py) * WW + tx0 + px0;

    if (g_maskv[b * KSEL + c] == 0.f) {
        if (c == g_padch[b]) {
            const uint2 z = make_uint2(0u, 0u);
            *(uint2*)&g_fusedb[obase] = z;   // plane 0 only (the pad row)
        }
        return;
    }

    const __nv_bfloat16* in = g_selb + ((size_t)(b * KSEL + c)) * HWPX;

    for (int i = t; i < 38 * 38; i += 256) {
        int r = i / 38, cc = i % 38;
        int gy = ty0 + r - 3, gx = tx0 + cc - 3;
        s[r][cc] = (gy >= 0 && gy < HH && gx >= 0 && gx < WW) ? __bfloat162float(in[gy * WW + gx]) : 0.f;
    }
    if (t < 9)        sw[t] = g_w3[(b * KSEL + c) * 9 + t];
    else if (t < 34)  sw[t] = g_w5[(b * KSEL + c) * 25 + (t - 9)];
    else if (t < 83)  sw[t] = g_w7[(b * KSEL + c) * 49 + (t - 34)];
    __syncthreads();

    float a3[4] = {0.f, 0.f, 0.f, 0.f};
    float a5[4] = {0.f, 0.f, 0.f, 0.f};
    float a7[4] = {0.f, 0.f, 0.f, 0.f};

#pragma unroll
    for (int dy = 0; dy < 7; dy++) {
        const float* row = &s[py + dy][0];
        float4 v0 = *(const float4*)&row[px0];
        float4 v1 = *(const float4*)&row[px0 + 4];
        float4 v2 = *(const float4*)&row[px0 + 8];
        float w[12] = {v0.x, v0.y, v0.z, v0.w, v1.x, v1.y, v1.z, v1.w,
                       v2.x, v2.y, v2.z, v2.w};
#pragma unroll
        for (int dx = 0; dx < 7; dx++) {
            float wt = sw[34 + dy * 7 + dx];
#pragma unroll
            for (int j = 0; j < 4; j++) a7[j] = fmaf(w[j + dx], wt, a7[j]);
        }
        if (dy >= 1 && dy <= 5) {
#pragma unroll
            for (int dx = 0; dx < 5; dx++) {
                float wt = sw[9 + (dy - 1) * 5 + dx];
#pragma unroll
                for (int j = 0; j < 4; j++) a5[j] = fmaf(w[j + 1 + dx], wt, a5[j]);
            }
        }
        if (dy >= 2 && dy <= 4) {
#pragma unroll
            for (int dx = 0; dx < 3; dx++) {
                float wt = sw[(dy - 2) * 3 + dx];
#pragma unroll
                for (int j = 0; j < 4; j++) a3[j] = fmaf(w[j + 2 + dx], wt, a3[j]);
            }
        }
    }

    {
        __nv_bfloat162 p0 = __floats2bfloat162_rn(a3[0], a3[1]);
        __nv_bfloat162 p1 = __floats2bfloat162_rn(a3[2], a3[3]);
        *(uint2*)&g_fusedb[obase] = make_uint2(*(uint32_t*)&p0, *(uint32_t*)&p1);
        p0 = __floats2bfloat162_rn(a5[0], a5[1]);
        p1 = __floats2bfloat162_rn(a5[2], a5[3]);
        *(uint2*)&g_fusedb[obase + (size_t)KSEL * HWPX] = make_uint2(*(uint32_t*)&p0, *(uint32_t*)&p1);
        p0 = __floats2bfloat162_rn(a7[0], a7[1]);
        p1 = __floats2bfloat162_rn(a7[2], a7[3]);
        *(uint2*)&g_fusedb[obase + (size_t)2 * KSEL * HWPX] = make_uint2(*(uint32_t*)&p0, *(uint32_t*)&p1);
    }
}

// =====================================================================
extern "C" void kernel_launch(void* const* d_in, const int* in_sizes, int n_in,
                              void* d_out, int out_size)
{
    const float* x     = (const float*)d_in[0];
    const float* pw1_w = (const float*)d_in[1];
    const float* pw1_b = (const float*)d_in[2];
    const float* fc1_w = (const float*)d_in[3];
    const float* fc1_b = (const float*)d_in[4];
    const float* fc2_w = (const float*)d_in[5];
    const float* fc2_b = (const float*)d_in[6];
    const float* off_w = (const float*)d_in[7];
    const float* off_b = (const float*)d_in[8];
    const float* dw3   = (const float*)d_in[9];
    const float* dw5   = (const float*)d_in[10];
    const float* dw7   = (const float*)d_in[11];
    const float* pw_w  = (const float*)d_in[12];
    const float* pw_b  = (const float*)d_in[13];
    float* out = (float*)d_out;

    const int smem1 = 256 * 256 * 2 + 2 * 16384 + 4 * 256 * 4 + 256;   // 168192
    const int smem2 = 256 * 384 * 2 + 2 * 16384 + 256;                  // 229632
    cudaFuncSetAttribute((const void*)kgemm<256, 1>, cudaFuncAttributeMaxDynamicSharedMemorySize, smem1);
    cudaFuncSetAttribute((const void*)kgemm2s, cudaFuncAttributeMaxDynamicSharedMemorySize, smem2);

    __nv_bfloat16 *gA1p, *gXbp;
    cudaGetSymbolAddress((void**)&gA1p, gA1);
    cudaGetSymbolAddress((void**)&gXbp, gXb);

    kxc<<<BATCH * CIN, 256>>>(x);
    kprep<<<256, 256>>>(pw1_w);
    kgemm<256, 1><<<dim3(128, 1, BATCH), 256, smem1>>>(gA1p, gXbp, pw1_b, nullptr, nullptr);
    k2a<<<288, 256>>>(pw1_w, pw1_b);
    k2b<<<64, 256>>>(fc1_w, fc1_b);
    k2c<<<32, 256>>>(fc2_w, fc2_b);
    k2d<<<64, 256>>>(off_w, off_b, dw3, dw5, dw7);
    kprep2<<<dim3(256, BATCH), 256>>>(pw_w);
    k3_dwconv<<<dim3(16, KSEL, BATCH), 256>>>();
    kgemm2s<<<dim3(128, 1, BATCH), 256, smem2>>>(pw_b, x, out);
}

// round 14
// speedup vs baseline: 1.7528x; 1.0066x over previous
#include <cuda_runtime.h>
#include <cuda_bf16.h>
#include <cstdint>
#include <math.h>

#define BATCH 8
#define CIN   256
#define MCH   256
#define OCH   256
#define HH    128
#define WW    128
#define HWPX  16384
#define KSEL  128

// ---------------- device scratch ----------------
__device__ __align__(128) __nv_bfloat16 gXb[(size_t)BATCH * CIN * HWPX];           // x bf16
__device__ __align__(128) __nv_bfloat16 g_selb[(size_t)BATCH * KSEL * HWPX];       // relu(h)[:,:128] bf16
__device__ __align__(128) __nv_bfloat16 g_fusedb[(size_t)BATCH * 3 * KSEL * HWPX]; // dwconv out bf16
__device__ __align__(128) __nv_bfloat16 gA1[256 * 256];                            // pw1_w bf16 linear
__device__ __align__(128) __nv_bfloat16 gA2b[(size_t)BATCH * 256 * 384];           // per-batch GATHERED pw_w bf16
__device__ float gXmean[BATCH * CIN];
__device__ float g_gap2_part[BATCH * MCH * 128];
__device__ float g_gapv[BATCH * MCH];
__device__ float g_gap2v[BATCH * MCH];
__device__ float g_hidv[BATCH * 512];
__device__ float g_scorev[BATCH * MCH];
__device__ float g_maskv[BATCH * KSEL];
__device__ int   g_rowsrc[BATCH * 384];
__device__ int   g_kp[BATCH];
__device__ int   g_padch[BATCH];
__device__ float g_w3[BATCH * KSEL * 9];
__device__ float g_w5[BATCH * KSEL * 25];
__device__ float g_w7[BATCH * KSEL * 49];

// ---------------- PTX helpers ----------------
__device__ __forceinline__ uint32_t smem_u32(const void* p) {
    uint32_t a;
    asm("{ .reg .u64 t; cvta.to.shared.u64 t, %1; cvt.u32.u64 %0, t; }" : "=r"(a) : "l"(p));
    return a;
}
__device__ __forceinline__ void cp16(uint32_t dst, const void* src) {
    asm volatile("cp.async.cg.shared.global [%0], [%1], 16;" :: "r"(dst), "l"(src) : "memory");
}
__device__ __forceinline__ void cp_commit() { asm volatile("cp.async.commit_group;" ::: "memory"); }
template<int N> __device__ __forceinline__ void cp_wait() { asm volatile("cp.async.wait_group %0;" :: "n"(N) : "memory"); }

__device__ __forceinline__ void ldsm_x4(uint32_t* r, uint32_t addr) {
    asm volatile("ldmatrix.sync.aligned.m8n8.x4.shared.b16 {%0,%1,%2,%3}, [%4];"
                 : "=r"(r[0]), "=r"(r[1]), "=r"(r[2]), "=r"(r[3]) : "r"(addr));
}
__device__ __forceinline__ void ldsm_x4_t(uint32_t* r, uint32_t addr) {
    asm volatile("ldmatrix.sync.aligned.m8n8.x4.trans.shared.b16 {%0,%1,%2,%3}, [%4];"
                 : "=r"(r[0]), "=r"(r[1]), "=r"(r[2]), "=r"(r[3]) : "r"(addr));
}
__device__ __forceinline__ void mma16816(float* d, const uint32_t* a, const uint32_t* b) {
    asm volatile("mma.sync.aligned.m16n8k16.row.col.f32.bf16.bf16.f32 "
                 "{%0,%1,%2,%3}, {%4,%5,%6,%7}, {%8,%9}, {%0,%1,%2,%3};"
                 : "+f"(d[0]), "+f"(d[1]), "+f"(d[2]), "+f"(d[3])
                 : "r"(a[0]), "r"(a[1]), "r"(a[2]), "r"(a[3]), "r"(b[0]), "r"(b[1]));
}
__device__ __forceinline__ float wred(float v) {
    v += __shfl_xor_sync(0xffffffffu, v, 16);
    v += __shfl_xor_sync(0xffffffffu, v, 8);
    v += __shfl_xor_sync(0xffffffffu, v, 4);
    v += __shfl_xor_sync(0xffffffffu, v, 2);
    v += __shfl_xor_sync(0xffffffffu, v, 1);
    return v;
}

// =====================================================================
// kxc: x fp32 -> bf16 + exact fp32 row means
// =====================================================================
__global__ __launch_bounds__(256) void kxc(const float* __restrict__ x)
{
    __shared__ float red[256];
    const int row = blockIdx.x;
    const int t = threadIdx.x;
    const float4* in4 = (const float4*)(x + (size_t)row * HWPX);
    __nv_bfloat162* ob = (__nv_bfloat162*)(gXb + (size_t)row * HWPX);
    float s = 0.f;
#pragma unroll
    for (int it = 0; it < 16; it++) {
        int j = t + it * 256;
        float4 v = in4[j];
        s += v.x + v.y + v.z + v.w;
        ob[j * 2 + 0] = __floats2bfloat162_rn(v.x, v.y);
        ob[j * 2 + 1] = __floats2bfloat162_rn(v.z, v.w);
    }
    red[t] = s;
    __syncthreads();
    for (int o = 128; o > 0; o >>= 1) {
        if (t < o) red[t] += red[t + o];
        __syncthreads();
    }
    if (t == 0) gXmean[row] = red[0] * (1.f / (float)HWPX);
}

// =====================================================================
// kprep: pw1_w -> bf16 linear
// =====================================================================
__global__ __launch_bounds__(256) void kprep(const float* __restrict__ pw1_w)
{
    int i = blockIdx.x * 256 + threadIdx.x;
    gA1[i] = __float2bfloat16(pw1_w[i]);
}

// =====================================================================
// kgemm<KDIM, EP=1> (R14: 4m x 2p warps, warp tile 64m x 64p):
// -20% ldsm vs R8 layout; per-output K order unchanged.
// grid (128, 1, BATCH), 256 threads.
// =====================================================================
template<int KDIM, int EP>
__global__ __launch_bounds__(256, 1)
void kgemm(const __nv_bfloat16* __restrict__ Aimg,
           const __nv_bfloat16* __restrict__ Bsrc,
           const float* __restrict__ bias,
           const float* __restrict__ xres,
           float* __restrict__ out)
{
    constexpr int KC = 64;
    constexpr int NCHUNK = KDIM / KC;
    constexpr int ASZ = 256 * KDIM * 2;
    constexpr int BROW = 256;
    constexpr int BSZ = KC * BROW;

    extern __shared__ char sraw[];
    const uint32_t rawu = smem_u32(sraw);
    const uint32_t sbase = (rawu + 127u) & ~127u;
    const uint32_t uA = sbase;
    const uint32_t uB = sbase + ASZ;
    float* sg = (float*)(sraw + (sbase - rawu) + ASZ + 2 * BSZ);   // [2][256]

    const int t = threadIdx.x, wid = t >> 5, lane = t & 31;
    const int b = blockIdx.z, pc = blockIdx.x;
    const int p0 = pc * 128;
    const int wm = (wid >> 1) * 64;          // warp m offset (0/64/128/192)
    const int wp = (wid & 1) * 64;           // warp p offset (0/64)

    const char* Bb = (const char*)(Bsrc + (size_t)b * KDIM * HWPX);
    const char* Ab = (const char*)Aimg;

    {
        constexpr int CPR = KDIM / 8;
        for (int i = t; i < 256 * CPR; i += 256) {
            int m = i / CPR, j = i % CPR;
            cp16(uA + m * (KDIM * 2) + ((j * 16) ^ ((m & 7) << 4)),
                 Ab + (size_t)m * (KDIM * 2) + j * 16);
        }
    }
    auto loadB = [&](int buf, int kc0) {
        uint32_t dst = uB + buf * BSZ;
#pragma unroll
        for (int i = t; i < KC * 16; i += 256) {
            int k = i >> 4, j = i & 15;
            cp16(dst + k * BROW + ((j * 16) ^ ((k & 7) << 4)),
                 Bb + ((size_t)(kc0 + k) * HWPX + p0) * 2 + j * 16);
        }
    };
    loadB(0, 0);
    cp_commit();
    if (NCHUNK > 1) { loadB(1, KC); cp_commit(); }

    float acc[4][8][4];
#pragma unroll
    for (int mi = 0; mi < 4; mi++)
#pragma unroll
        for (int ni = 0; ni < 8; ni++)
#pragma unroll
            for (int r = 0; r < 4; r++) acc[mi][ni][r] = 0.f;

    const int a_m  = wm + (lane & 15);
    const int a_kb = (lane >> 4) * 16;
    const uint32_t aBase = uA + a_m * (KDIM * 2);
    const uint32_t aSwz  = (a_m & 7) << 4;
    const int b_k  = lane & 15;
    const int b_nb = wp * 2 + (lane >> 4) * 16;
    const uint32_t bSwzK = (b_k & 7) << 4;

    for (int c = 0; c < NCHUNK; c++) {
        if (c == NCHUNK - 1) cp_wait<0>(); else cp_wait<1>();   // R4 race fix
        __syncthreads();
        const uint32_t bb = uB + (c & 1) * BSZ + b_k * BROW;
#pragma unroll
        for (int ks = 0; ks < KC / 16; ks++) {
            const int kB = ks * 32;
            uint32_t bf[4][4];
#pragma unroll
            for (int h = 0; h < 4; h++)
                ldsm_x4_t(bf[h], bb + ks * 16 * BROW + ((b_nb + h * 32) ^ bSwzK));
#pragma unroll
            for (int mi = 0; mi < 4; mi++) {
                uint32_t a[4];
                ldsm_x4(a, aBase + mi * 16 * (KDIM * 2) +
                           (((c * KC * 2) + kB + a_kb) ^ aSwz));
#pragma unroll
                for (int ni = 0; ni < 8; ni++)
                    mma16816(acc[mi][ni], a, &bf[ni >> 1][(ni & 1) * 2]);
            }
        }
        __syncthreads();
        if (c + 2 < NCHUNK) { loadB(c & 1, (c + 2) * KC); cp_commit(); }
    }

    const int erow = lane >> 2;
    const int ecol = (lane & 3) * 2;
    if (EP == 2) {
#pragma unroll
        for (int mi = 0; mi < 4; mi++) {
#pragma unroll
            for (int h = 0; h < 2; h++) {
                const int m = wm + mi * 16 + h * 8 + erow;
                const float bv = bias[m];
                const size_t rb = ((size_t)(b * OCH + m)) * HWPX + p0;
#pragma unroll
                for (int ni = 0; ni < 8; ni++) {
                    const size_t o = rb + wp + ni * 8 + ecol;
                    float2 xr = *(const float2*)&xres[o];
                    float2 v;
                    v.x = acc[mi][ni][2 * h]     + bv + xr.x;
                    v.y = acc[mi][ni][2 * h + 1] + bv + xr.y;
                    *(float2*)&out[o] = v;
                }
            }
        }
    } else {
        float rs[4][2];
#pragma unroll
        for (int mi = 0; mi < 4; mi++) {
#pragma unroll
            for (int h = 0; h < 2; h++) {
                const int m = wm + mi * 16 + h * 8 + erow;
                const float bv = bias[m];
                float s2 = 0.f;
#pragma unroll
                for (int ni = 0; ni < 8; ni++) {
                    float v0 = fmaxf(acc[mi][ni][2 * h]     + bv, 0.f);
                    float v1 = fmaxf(acc[mi][ni][2 * h + 1] + bv, 0.f);
                    s2 += v0 + v1;
                    if (m < KSEL) {
                        size_t o = ((size_t)(b * KSEL + m)) * HWPX + p0 + wp + ni * 8 + ecol;
                        *(__nv_bfloat162*)&g_selb[o] = __floats2bfloat162_rn(v0, v1);
                    }
                }
                rs[mi][h] = s2;
            }
        }
#pragma unroll
        for (int mi = 0; mi < 4; mi++)
#pragma unroll
            for (int h = 0; h < 2; h++) {
                rs[mi][h] += __shfl_xor_sync(0xffffffffu, rs[mi][h], 1);
                rs[mi][h] += __shfl_xor_sync(0xffffffffu, rs[mi][h], 2);
            }
        if ((lane & 3) == 0) {
#pragma unroll
            for (int mi = 0; mi < 4; mi++)
#pragma unroll
                for (int h = 0; h < 2; h++)
                    sg[(wid & 1) * 256 + wm + mi * 16 + h * 8 + erow] = rs[mi][h];
        }
        __syncthreads();
        g_gap2_part[(b * MCH + t) * 128 + pc] = sg[t] + sg[256 + t];
    }
}

// =====================================================================
// kgemm2s (R14 layout): sparse-K GEMM2, 4m x 2p warps.
// grid (128, 1, BATCH), 256 threads.
// =====================================================================
__global__ __launch_bounds__(256, 1)
void kgemm2s(const float* __restrict__ bias,
             const float* __restrict__ xres,
             float* __restrict__ out)
{
    constexpr int KC = 64;
    constexpr int ASZmax = 256 * 384 * 2;
    constexpr int BROW = 256;
    constexpr int BSZ = KC * BROW;

    extern __shared__ char sraw[];
    const uint32_t rawu = smem_u32(sraw);
    const uint32_t sbase = (rawu + 127u) & ~127u;
    const uint32_t uA = sbase;
    const uint32_t uB = sbase + ASZmax;

    const int t = threadIdx.x, wid = t >> 5, lane = t & 31;
    const int b = blockIdx.z, pc = blockIdx.x;
    const int p0 = pc * 128;
    const int wm = (wid >> 1) * 64;
    const int wp = (wid & 1) * 64;

    const int kp = g_kp[b];
    const int nchunk = kp >> 6;
    const int* rs = g_rowsrc + b * 384;
    const char* Bb = (const char*)(g_fusedb + (size_t)b * 384 * HWPX);
    const char* Ab = (const char*)(gA2b + (size_t)b * 256 * 384);
    const int kp2 = kp * 2;

    {
        const int cpr = kp >> 3;
        for (int i = t; i < 256 * cpr; i += 256) {
            int m = i / cpr, j = i % cpr;
            cp16(uA + m * kp2 + ((j * 16) ^ ((m & 7) << 4)),
                 Ab + (size_t)m * kp2 + j * 16);
        }
    }
    auto loadB = [&](int buf, int kc0) {
        uint32_t dst = uB + buf * BSZ;
#pragma unroll
        for (int i = t; i < KC * 16; i += 256) {
            int k = i >> 4, j = i & 15;
            int row = rs[kc0 + k];
            cp16(dst + k * BROW + ((j * 16) ^ ((k & 7) << 4)),
                 Bb + ((size_t)row * HWPX + p0) * 2 + j * 16);
        }
    };
    loadB(0, 0);
    cp_commit();
    if (nchunk > 1) { loadB(1, KC); cp_commit(); }

    float acc[4][8][4];
#pragma unroll
    for (int mi = 0; mi < 4; mi++)
#pragma unroll
        for (int ni = 0; ni < 8; ni++)
#pragma unroll
            for (int r = 0; r < 4; r++) acc[mi][ni][r] = 0.f;

    const int a_m  = wm + (lane & 15);
    const int a_kb = (lane >> 4) * 16;
    const uint32_t aBase = uA + a_m * kp2;
    const uint32_t aSwz  = (a_m & 7) << 4;
    const int b_k  = lane & 15;
    const int b_nb = wp * 2 + (lane >> 4) * 16;
    const uint32_t bSwzK = (b_k & 7) << 4;

    for (int c = 0; c < nchunk; c++) {
        if (c == nchunk - 1) cp_wait<0>(); else cp_wait<1>();   // R4 race fix
        __syncthreads();
        const uint32_t bb = uB + (c & 1) * BSZ + b_k * BROW;
#pragma unroll
        for (int ks = 0; ks < KC / 16; ks++) {
            const int kB = ks * 32;
            uint32_t bf[4][4];
#pragma unroll
            for (int h = 0; h < 4; h++)
                ldsm_x4_t(bf[h], bb + ks * 16 * BROW + ((b_nb + h * 32) ^ bSwzK));
#pragma unroll
            for (int mi = 0; mi < 4; mi++) {
                uint32_t a[4];
                ldsm_x4(a, aBase + mi * 16 * kp2 +
                           (((c * KC * 2) + kB + a_kb) ^ aSwz));
#pragma unroll
                for (int ni = 0; ni < 8; ni++)
                    mma16816(acc[mi][ni], a, &bf[ni >> 1][(ni & 1) * 2]);
            }
        }
        __syncthreads();
        if (c + 2 < nchunk) { loadB(c & 1, (c + 2) * KC); cp_commit(); }
    }

    const int erow = lane >> 2;
    const int ecol = (lane & 3) * 2;
#pragma unroll
    for (int mi = 0; mi < 4; mi++) {
#pragma unroll
        for (int h = 0; h < 2; h++) {
            const int m = wm + mi * 16 + h * 8 + erow;
            const float bv = bias[m];
            const size_t rb = ((size_t)(b * OCH + m)) * HWPX + p0;
#pragma unroll
            for (int ni = 0; ni < 8; ni++) {
                const size_t o = rb + wp + ni * 8 + ecol;
                float2 xr = *(const float2*)&xres[o];
                float2 v;
                v.x = acc[mi][ni][2 * h]     + bv + xr.x;
                v.y = acc[mi][ni][2 * h + 1] + bv + xr.y;
                *(float2*)&out[o] = v;
            }
        }
    }
}

// =====================================================================
// k2a: gap (exact, from xmean) + gap2 partial reduce. grid 288.
// =====================================================================
__global__ __launch_bounds__(256) void k2a(const float* __restrict__ pw1_w,
                                           const float* __restrict__ pw1_b)
{
    const int t = threadIdx.x, wid = t >> 5, lane = t & 31;
    if (blockIdx.x < 32) {
        __shared__ float sxm[2048];
        for (int i = t; i < 2048; i += 256) sxm[i] = gXmean[i];
        __syncthreads();
        const int m = blockIdx.x * 8 + wid;
        const float* wr = pw1_w + m * CIN;
        float acc[8] = {0.f, 0.f, 0.f, 0.f, 0.f, 0.f, 0.f, 0.f};
        for (int c = lane; c < CIN; c += 32) {
            float w = wr[c];
#pragma unroll
            for (int bb = 0; bb < 8; bb++) acc[bb] = fmaf(sxm[bb * 256 + c], w, acc[bb]);
        }
#pragma unroll
        for (int bb = 0; bb < 8; bb++) acc[bb] = wred(acc[bb]);
        if (lane == 0) {
            float bv = pw1_b[m];
#pragma unroll
            for (int bb = 0; bb < 8; bb++) g_gapv[bb * 256 + m] = acc[bb] + bv;
        }
    } else {
        const int rr = (blockIdx.x - 32) * 8 + wid;
        const float4* p4 = (const float4*)(g_gap2_part + (size_t)rr * 128);
        float4 v = p4[lane];
        float a = wred(v.x + v.y + v.z + v.w);
        if (lane == 0) g_gap2v[rr] = a * (1.f / (float)HWPX);
    }
}

// =====================================================================
// k2b: fc1. grid 64, warp per j.
// =====================================================================
__global__ __launch_bounds__(256) void k2b(const float* __restrict__ fc1_w,
                                           const float* __restrict__ fc1_b)
{
    __shared__ float sgap[2048];
    const int t = threadIdx.x, wid = t >> 5, lane = t & 31;
    for (int i = t; i < 2048; i += 256) sgap[i] = g_gapv[i];
    __syncthreads();
    const int j = blockIdx.x * 8 + wid;
    const float* wr = fc1_w + j * MCH;
    float acc[8] = {0.f, 0.f, 0.f, 0.f, 0.f, 0.f, 0.f, 0.f};
    for (int c = lane; c < MCH; c += 32) {
        float w = wr[c];
#pragma unroll
        for (int bb = 0; bb < 8; bb++) acc[bb] = fmaf(sgap[bb * 256 + c], w, acc[bb]);
    }
#pragma unroll
    for (int bb = 0; bb < 8; bb++) acc[bb] = wred(acc[bb]);
    if (lane == 0) {
        float bv = fc1_b[j];
#pragma unroll
        for (int bb = 0; bb < 8; bb++) g_hidv[bb * 512 + j] = fmaxf(acc[bb] + bv, 0.f);
    }
}

// =====================================================================
// k2c: fc2 + sigmoid. grid 32, warp per j.
// =====================================================================
__global__ __launch_bounds__(256) void k2c(const float* __restrict__ fc2_w,
                                           const float* __restrict__ fc2_b)
{
    __shared__ float shid[4096];
    const int t = threadIdx.x, wid = t >> 5, lane = t & 31;
    for (int i = t; i < 4096; i += 256) shid[i] = g_hidv[i];
    __syncthreads();
    const int j = blockIdx.x * 8 + wid;
    const float* wr = fc2_w + j * 512;
    float acc[8] = {0.f, 0.f, 0.f, 0.f, 0.f, 0.f, 0.f, 0.f};
    for (int c = lane; c < 512; c += 32) {
        float w = wr[c];
#pragma unroll
        for (int bb = 0; bb < 8; bb++) acc[bb] = fmaf(shid[bb * 512 + c], w, acc[bb]);
    }
#pragma unroll
    for (int bb = 0; bb < 8; bb++) acc[bb] = wred(acc[bb]);
    if (lane == 0) {
        float bv = fc2_b[j];
#pragma unroll
        for (int bb = 0; bb < 8; bb++)
            g_scorev[bb * 256 + j] = 1.f / (1.f + expf(-(acc[bb] + bv)));
    }
}

// =====================================================================
// k2d: top-k mask + offsets + effective dw weights + sparsity metadata.
// grid 64 = 8 batches x 8 slices.
// =====================================================================
__global__ __launch_bounds__(256) void k2d(const float* __restrict__ off_w,
                                           const float* __restrict__ off_b,
                                           const float* __restrict__ dw3,
                                           const float* __restrict__ dw5,
                                           const float* __restrict__ dw7)
{
    __shared__ float ssc[256], sg2[256], smask[128], sscl[3], ssht[3];
    const int t = threadIdx.x, wid = t >> 5, lane = t & 31;
    const int bb = blockIdx.x >> 3, slice = blockIdx.x & 7;

    ssc[t] = g_scorev[bb * 256 + t];
    sg2[t] = g_gap2v[bb * 256 + t];
    __syncthreads();

    if (wid < 6) {
        const int r = wid;
        const float* wr = off_w + r * MCH;
        float a = 0.f;
        for (int c = lane; c < MCH; c += 32) a = fmaf(sg2[c], wr[c], a);
        a = wred(a);
        if (lane == 0) {
            float o = tanhf(a + off_b[r]);
            if ((r & 1) == 0) sscl[r >> 1] = 1.f / (1.f + expf(-o));
            else              ssht[r >> 1] = tanhf(o);
        }
    }
    if (t < KSEL) {
        float sc = ssc[t];
        int cnt = 0;
        for (int j = 0; j < MCH; j++) {
            float sj = ssc[j];
            cnt += (sj > sc) || (sj == sc && j < t);
        }
        float mk = (cnt < KSEL) ? 1.f : 0.f;
        smask[t] = mk;
        if (slice == 0) g_maskv[bb * KSEL + t] = mk;
    }
    __syncthreads();

    if (slice == 0 && t < 128) {
        int pos = 0, katot = 0, padc = -1;
        for (int j = 0; j < 128; j++) {
            int a = (smask[j] > 0.f);
            katot += a;
            if (j < t) pos += a;
            if (!a && padc < 0) padc = j;
        }
        if (smask[t] > 0.f) {
#pragma unroll
            for (int g = 0; g < 3; g++)
                g_rowsrc[bb * 384 + g * katot + pos] = g * 128 + t;
        }
        int kp = ((3 * katot + 63) >> 6) << 6;
        if (kp == 0) kp = 64;
        int npad = kp - 3 * katot;
        if (t < npad) g_rowsrc[bb * 384 + 3 * katot + t] = (padc >= 0 ? padc : 0);
        if (t == 0) { g_kp[bb] = kp; g_padch[bb] = padc; }
    }

    for (int i = slice * 256 + t; i < 1152; i += 2048) {
        int c = i / 9;
        g_w3[bb * 1152 + i] = fmaf(dw3[i], 1.f + sscl[0], ssht[0]) * smask[c];
    }
    for (int i = slice * 256 + t; i < 3200; i += 2048) {
        int c = i / 25;
        g_w5[bb * 3200 + i] = fmaf(dw5[i], 1.f + sscl[1], ssht[1]) * smask[c];
    }
    for (int i = slice * 256 + t; i < 6272; i += 2048) {
        int c = i / 49;
        g_w7[bb * 6272 + i] = fmaf(dw7[i], 1.f + sscl[2], ssht[2]) * smask[c];
    }
}

// =====================================================================
// kprep2: per-batch gathered A' for sparse GEMM2. grid (256, 8).
// =====================================================================
__global__ __launch_bounds__(256) void kprep2(const float* __restrict__ pw_w)
{
    const int m = blockIdx.x, b = blockIdx.y;
    const int kp = g_kp[b];
    const int* rs = g_rowsrc + b * 384;
    __nv_bfloat16* dst = gA2b + (size_t)b * 256 * 384 + (size_t)m * kp;
    const float* src = pw_w + (size_t)m * 768;
    for (int kk = threadIdx.x; kk < kp; kk += 256)
        dst[kk] = __float2bfloat16(src[rs[kk]]);
}

// =====================================================================
// k3 (R12/R13, protected): scalar dwconv, masked-channel skip.
// =====================================================================
__global__ __launch_bounds__(256) void k3_dwconv()
{
    __shared__ float s[38][40];
    __shared__ float sw[84];

    const int b = blockIdx.z;
    const int c = blockIdx.y;
    const int tile = blockIdx.x;
    const int ty0 = (tile >> 2) * 32;
    const int tx0 = (tile & 3) * 32;
    const int t = threadIdx.x;

    const int py  = t >> 3;
    const int px0 = (t & 7) * 4;
    const size_t obase = ((size_t)(b * (3 * KSEL) + c)) * HWPX + (size_t)(ty0 + py) * WW + tx0 + px0;

    if (g_maskv[b * KSEL + c] == 0.f) {
        if (c == g_padch[b]) {
            const uint2 z = make_uint2(0u, 0u);
            *(uint2*)&g_fusedb[obase] = z;
        }
        return;
    }

    const __nv_bfloat16* in = g_selb + ((size_t)(b * KSEL + c)) * HWPX;

    for (int i = t; i < 38 * 38; i += 256) {
        int r = i / 38, cc = i % 38;
        int gy = ty0 + r - 3, gx = tx0 + cc - 3;
        s[r][cc] = (gy >= 0 && gy < HH && gx >= 0 && gx < WW) ? __bfloat162float(in[gy * WW + gx]) : 0.f;
    }
    if (t < 9)        sw[t] = g_w3[(b * KSEL + c) * 9 + t];
    else if (t < 34)  sw[t] = g_w5[(b * KSEL + c) * 25 + (t - 9)];
    else if (t < 83)  sw[t] = g_w7[(b * KSEL + c) * 49 + (t - 34)];
    __syncthreads();

    float a3[4] = {0.f, 0.f, 0.f, 0.f};
    float a5[4] = {0.f, 0.f, 0.f, 0.f};
    float a7[4] = {0.f, 0.f, 0.f, 0.f};

#pragma unroll
    for (int dy = 0; dy < 7; dy++) {
        const float* row = &s[py + dy][0];
        float4 v0 = *(const float4*)&row[px0];
        float4 v1 = *(const float4*)&row[px0 + 4];
        float4 v2 = *(const float4*)&row[px0 + 8];
        float w[12] = {v0.x, v0.y, v0.z, v0.w, v1.x, v1.y, v1.z, v1.w,
                       v2.x, v2.y, v2.z, v2.w};
#pragma unroll
        for (int dx = 0; dx < 7; dx++) {
            float wt = sw[34 + dy * 7 + dx];
#pragma unroll
            for (int j = 0; j < 4; j++) a7[j] = fmaf(w[j + dx], wt, a7[j]);
        }
        if (dy >= 1 && dy <= 5) {
#pragma unroll
            for (int dx = 0; dx < 5; dx++) {
                float wt = sw[9 + (dy - 1) * 5 + dx];
#pragma unroll
                for (int j = 0; j < 4; j++) a5[j] = fmaf(w[j + 1 + dx], wt, a5[j]);
            }
        }
        if (dy >= 2 && dy <= 4) {
#pragma unroll
            for (int dx = 0; dx < 3; dx++) {
                float wt = sw[(dy - 2) * 3 + dx];
#pragma unroll
                for (int j = 0; j < 4; j++) a3[j] = fmaf(w[j + 2 + dx], wt, a3[j]);
            }
        }
    }

    {
        __nv_bfloat162 p0 = __floats2bfloat162_rn(a3[0], a3[1]);
        __nv_bfloat162 p1 = __floats2bfloat162_rn(a3[2], a3[3]);
        *(uint2*)&g_fusedb[obase] = make_uint2(*(uint32_t*)&p0, *(uint32_t*)&p1);
        p0 = __floats2bfloat162_rn(a5[0], a5[1]);
        p1 = __floats2bfloat162_rn(a5[2], a5[3]);
        *(uint2*)&g_fusedb[obase + (size_t)KSEL * HWPX] = make_uint2(*(uint32_t*)&p0, *(uint32_t*)&p1);
        p0 = __floats2bfloat162_rn(a7[0], a7[1]);
        p1 = __floats2bfloat162_rn(a7[2], a7[3]);
        *(uint2*)&g_fusedb[obase + (size_t)2 * KSEL * HWPX] = make_uint2(*(uint32_t*)&p0, *(uint32_t*)&p1);
    }
}

// =====================================================================
extern "C" void kernel_launch(void* const* d_in, const int* in_sizes, int n_in,
                              void* d_out, int out_size)
{
    const float* x     = (const float*)d_in[0];
    const float* pw1_w = (const float*)d_in[1];
    const float* pw1_b = (const float*)d_in[2];
    const float* fc1_w = (const float*)d_in[3];
    const float* fc1_b = (const float*)d_in[4];
    const float* fc2_w = (const float*)d_in[5];
    const float* fc2_b = (const float*)d_in[6];
    const float* off_w = (const float*)d_in[7];
    const float* off_b = (const float*)d_in[8];
    const float* dw3   = (const float*)d_in[9];
    const float* dw5   = (const float*)d_in[10];
    const float* dw7   = (const float*)d_in[11];
    const float* pw_w  = (const float*)d_in[12];
    const float* pw_b  = (const float*)d_in[13];
    float* out = (float*)d_out;

    const int smem1 = 256 * 256 * 2 + 2 * 16384 + 2 * 256 * 4 + 256;   // ~166KB
    const int smem2 = 256 * 384 * 2 + 2 * 16384 + 256;                  // 229632
    cudaFuncSetAttribute((const void*)kgemm<256, 1>, cudaFuncAttributeMaxDynamicSharedMemorySize, smem1);
    cudaFuncSetAttribute((const void*)kgemm2s, cudaFuncAttributeMaxDynamicSharedMemorySize, smem2);

    __nv_bfloat16 *gA1p, *gXbp;
    cudaGetSymbolAddress((void**)&gA1p, gA1);
    cudaGetSymbolAddress((void**)&gXbp, gXb);

    kxc<<<BATCH * CIN, 256>>>(x);
    kprep<<<256, 256>>>(pw1_w);
    kgemm<256, 1><<<dim3(128, 1, BATCH), 256, smem1>>>(gA1p, gXbp, pw1_b, nullptr, nullptr);
    k2a<<<288, 256>>>(pw1_w, pw1_b);
    k2b<<<64, 256>>>(fc1_w, fc1_b);
    k2c<<<32, 256>>>(fc2_w, fc2_b);
    k2d<<<64, 256>>>(off_w, off_b, dw3, dw5, dw7);
    kprep2<<<dim3(256, BATCH), 256>>>(pw_w);
    k3_dwconv<<<dim3(16, KSEL, BATCH), 256>>>();
    kgemm2s<<<dim3(128, 1, BATCH), 256, smem2>>>(pw_b, x, out);
}

// round 15
// speedup vs baseline: 1.8438x; 1.0519x over previous
#include <cuda_runtime.h>
#include <cuda_bf16.h>
#include <cstdint>
#include <math.h>

#define BATCH 8
#define CIN   256
#define MCH   256
#define OCH   256
#define HH    128
#define WW    128
#define HWPX  16384
#define KSEL  128

// ---------------- device scratch ----------------
__device__ __align__(128) __nv_bfloat16 gXb[(size_t)BATCH * CIN * HWPX];
__device__ __align__(128) __nv_bfloat16 g_selb[(size_t)BATCH * KSEL * HWPX];
__device__ __align__(128) __nv_bfloat16 g_fusedb[(size_t)BATCH * 3 * KSEL * HWPX];
__device__ __align__(128) __nv_bfloat16 gA1[256 * 256];
__device__ __align__(128) __nv_bfloat16 gA2b[(size_t)BATCH * 256 * 384];
__device__ float gXmean[BATCH * CIN];
__device__ float g_gap2_part[BATCH * MCH * 128];
__device__ float g_gapv[BATCH * MCH];
__device__ float g_gap2v[BATCH * MCH];
__device__ float g_hidv[BATCH * 512];
__device__ float g_scorev[BATCH * MCH];
__device__ float g_maskv[BATCH * KSEL];
__device__ int   g_rowsrc[BATCH * 384];
__device__ int   g_kp[BATCH];
__device__ int   g_padch[BATCH];
__device__ float g_w3[BATCH * KSEL * 9];
__device__ float g_w5[BATCH * KSEL * 25];
__device__ float g_w7[BATCH * KSEL * 49];

// ---------------- PTX helpers ----------------
__device__ __forceinline__ uint32_t smem_u32(const void* p) {
    uint32_t a;
    asm("{ .reg .u64 t; cvta.to.shared.u64 t, %1; cvt.u32.u64 %0, t; }" : "=r"(a) : "l"(p));
    return a;
}
__device__ __forceinline__ void cp16(uint32_t dst, const void* src) {
    asm volatile("cp.async.cg.shared.global [%0], [%1], 16;" :: "r"(dst), "l"(src) : "memory");
}
__device__ __forceinline__ void cp_commit() { asm volatile("cp.async.commit_group;" ::: "memory"); }
template<int N> __device__ __forceinline__ void cp_wait() { asm volatile("cp.async.wait_group %0;" :: "n"(N) : "memory"); }

__device__ __forceinline__ void ldsm_x4(uint32_t* r, uint32_t addr) {
    asm volatile("ldmatrix.sync.aligned.m8n8.x4.shared.b16 {%0,%1,%2,%3}, [%4];"
                 : "=r"(r[0]), "=r"(r[1]), "=r"(r[2]), "=r"(r[3]) : "r"(addr));
}
__device__ __forceinline__ void ldsm_x4_t(uint32_t* r, uint32_t addr) {
    asm volatile("ldmatrix.sync.aligned.m8n8.x4.trans.shared.b16 {%0,%1,%2,%3}, [%4];"
                 : "=r"(r[0]), "=r"(r[1]), "=r"(r[2]), "=r"(r[3]) : "r"(addr));
}
__device__ __forceinline__ void mma16816(float* d, const uint32_t* a, const uint32_t* b) {
    asm volatile("mma.sync.aligned.m16n8k16.row.col.f32.bf16.bf16.f32 "
                 "{%0,%1,%2,%3}, {%4,%5,%6,%7}, {%8,%9}, {%0,%1,%2,%3};"
                 : "+f"(d[0]), "+f"(d[1]), "+f"(d[2]), "+f"(d[3])
                 : "r"(a[0]), "r"(a[1]), "r"(a[2]), "r"(a[3]), "r"(b[0]), "r"(b[1]));
}
__device__ __forceinline__ float wred(float v) {
    v += __shfl_xor_sync(0xffffffffu, v, 16);
    v += __shfl_xor_sync(0xffffffffu, v, 8);
    v += __shfl_xor_sync(0xffffffffu, v, 4);
    v += __shfl_xor_sync(0xffffffffu, v, 2);
    v += __shfl_xor_sync(0xffffffffu, v, 1);
    return v;
}

// =====================================================================
// kxc: x fp32 -> bf16 + exact fp32 row means
// =====================================================================
__global__ __launch_bounds__(256) void kxc(const float* __restrict__ x)
{
    __shared__ float red[256];
    const int row = blockIdx.x;
    const int t = threadIdx.x;
    const float4* in4 = (const float4*)(x + (size_t)row * HWPX);
    __nv_bfloat162* ob = (__nv_bfloat162*)(gXb + (size_t)row * HWPX);
    float s = 0.f;
#pragma unroll
    for (int it = 0; it < 16; it++) {
        int j = t + it * 256;
        float4 v = in4[j];
        s += v.x + v.y + v.z + v.w;
        ob[j * 2 + 0] = __floats2bfloat162_rn(v.x, v.y);
        ob[j * 2 + 1] = __floats2bfloat162_rn(v.z, v.w);
    }
    red[t] = s;
    __syncthreads();
    for (int o = 128; o > 0; o >>= 1) {
        if (t < o) red[t] += red[t + o];
        __syncthreads();
    }
    if (t == 0) gXmean[row] = red[0] * (1.f / (float)HWPX);
}

// =====================================================================
// kprep: pw1_w -> bf16 linear
// =====================================================================
__global__ __launch_bounds__(256) void kprep(const float* __restrict__ pw1_w)
{
    int i = blockIdx.x * 256 + threadIdx.x;
    gA1[i] = __float2bfloat16(pw1_w[i]);
}

// =====================================================================
// kgemm<KDIM, EP=1> (R14 layout, frozen): 4m x 2p warps, 64m x 64p tiles.
// grid (128, 1, BATCH), 256 threads.
// =====================================================================
template<int KDIM, int EP>
__global__ __launch_bounds__(256, 1)
void kgemm(const __nv_bfloat16* __restrict__ Aimg,
           const __nv_bfloat16* __restrict__ Bsrc,
           const float* __restrict__ bias,
           const float* __restrict__ xres,
           float* __restrict__ out)
{
    constexpr int KC = 64;
    constexpr int NCHUNK = KDIM / KC;
    constexpr int ASZ = 256 * KDIM * 2;
    constexpr int BROW = 256;
    constexpr int BSZ = KC * BROW;

    extern __shared__ char sraw[];
    const uint32_t rawu = smem_u32(sraw);
    const uint32_t sbase = (rawu + 127u) & ~127u;
    const uint32_t uA = sbase;
    const uint32_t uB = sbase + ASZ;
    float* sg = (float*)(sraw + (sbase - rawu) + ASZ + 2 * BSZ);   // [2][256]

    const int t = threadIdx.x, wid = t >> 5, lane = t & 31;
    const int b = blockIdx.z, pc = blockIdx.x;
    const int p0 = pc * 128;
    const int wm = (wid >> 1) * 64;
    const int wp = (wid & 1) * 64;

    const char* Bb = (const char*)(Bsrc + (size_t)b * KDIM * HWPX);
    const char* Ab = (const char*)Aimg;

    {
        constexpr int CPR = KDIM / 8;
        for (int i = t; i < 256 * CPR; i += 256) {
            int m = i / CPR, j = i % CPR;
            cp16(uA + m * (KDIM * 2) + ((j * 16) ^ ((m & 7) << 4)),
                 Ab + (size_t)m * (KDIM * 2) + j * 16);
        }
    }
    auto loadB = [&](int buf, int kc0) {
        uint32_t dst = uB + buf * BSZ;
#pragma unroll
        for (int i = t; i < KC * 16; i += 256) {
            int k = i >> 4, j = i & 15;
            cp16(dst + k * BROW + ((j * 16) ^ ((k & 7) << 4)),
                 Bb + ((size_t)(kc0 + k) * HWPX + p0) * 2 + j * 16);
        }
    };
    loadB(0, 0);
    cp_commit();
    if (NCHUNK > 1) { loadB(1, KC); cp_commit(); }

    float acc[4][8][4];
#pragma unroll
    for (int mi = 0; mi < 4; mi++)
#pragma unroll
        for (int ni = 0; ni < 8; ni++)
#pragma unroll
            for (int r = 0; r < 4; r++) acc[mi][ni][r] = 0.f;

    const int a_m  = wm + (lane & 15);
    const int a_kb = (lane >> 4) * 16;
    const uint32_t aBase = uA + a_m * (KDIM * 2);
    const uint32_t aSwz  = (a_m & 7) << 4;
    const int b_k  = lane & 15;
    const int b_nb = wp * 2 + (lane >> 4) * 16;
    const uint32_t bSwzK = (b_k & 7) << 4;

    for (int c = 0; c < NCHUNK; c++) {
        if (c == NCHUNK - 1) cp_wait<0>(); else cp_wait<1>();   // R4 race fix
        __syncthreads();
        const uint32_t bb = uB + (c & 1) * BSZ + b_k * BROW;
#pragma unroll
        for (int ks = 0; ks < KC / 16; ks++) {
            const int kB = ks * 32;
            uint32_t bf[4][4];
#pragma unroll
            for (int h = 0; h < 4; h++)
                ldsm_x4_t(bf[h], bb + ks * 16 * BROW + ((b_nb + h * 32) ^ bSwzK));
#pragma unroll
            for (int mi = 0; mi < 4; mi++) {
                uint32_t a[4];
                ldsm_x4(a, aBase + mi * 16 * (KDIM * 2) +
                           (((c * KC * 2) + kB + a_kb) ^ aSwz));
#pragma unroll
                for (int ni = 0; ni < 8; ni++)
                    mma16816(acc[mi][ni], a, &bf[ni >> 1][(ni & 1) * 2]);
            }
        }
        __syncthreads();
        if (c + 2 < NCHUNK) { loadB(c & 1, (c + 2) * KC); cp_commit(); }
    }

    const int erow = lane >> 2;
    const int ecol = (lane & 3) * 2;
    {
        float rs[4][2];
#pragma unroll
        for (int mi = 0; mi < 4; mi++) {
#pragma unroll
            for (int h = 0; h < 2; h++) {
                const int m = wm + mi * 16 + h * 8 + erow;
                const float bv = bias[m];
                float s2 = 0.f;
#pragma unroll
                for (int ni = 0; ni < 8; ni++) {
                    float v0 = fmaxf(acc[mi][ni][2 * h]     + bv, 0.f);
                    float v1 = fmaxf(acc[mi][ni][2 * h + 1] + bv, 0.f);
                    s2 += v0 + v1;
                    if (m < KSEL) {
                        size_t o = ((size_t)(b * KSEL + m)) * HWPX + p0 + wp + ni * 8 + ecol;
                        *(__nv_bfloat162*)&g_selb[o] = __floats2bfloat162_rn(v0, v1);
                    }
                }
                rs[mi][h] = s2;
            }
        }
#pragma unroll
        for (int mi = 0; mi < 4; mi++)
#pragma unroll
            for (int h = 0; h < 2; h++) {
                rs[mi][h] += __shfl_xor_sync(0xffffffffu, rs[mi][h], 1);
                rs[mi][h] += __shfl_xor_sync(0xffffffffu, rs[mi][h], 2);
            }
        if ((lane & 3) == 0) {
#pragma unroll
            for (int mi = 0; mi < 4; mi++)
#pragma unroll
                for (int h = 0; h < 2; h++)
                    sg[(wid & 1) * 256 + wm + mi * 16 + h * 8 + erow] = rs[mi][h];
        }
        __syncthreads();
        g_gap2_part[(b * MCH + t) * 128 + pc] = sg[t] + sg[256 + t];
    }
}

// =====================================================================
// kgemm2s (R14 layout, frozen): sparse-K GEMM2, 4m x 2p warps.
// =====================================================================
__global__ __launch_bounds__(256, 1)
void kgemm2s(const float* __restrict__ bias,
             const float* __restrict__ xres,
             float* __restrict__ out)
{
    constexpr int KC = 64;
    constexpr int ASZmax = 256 * 384 * 2;
    constexpr int BROW = 256;
    constexpr int BSZ = KC * BROW;

    extern __shared__ char sraw[];
    const uint32_t rawu = smem_u32(sraw);
    const uint32_t sbase = (rawu + 127u) & ~127u;
    const uint32_t uA = sbase;
    const uint32_t uB = sbase + ASZmax;

    const int t = threadIdx.x, wid = t >> 5, lane = t & 31;
    const int b = blockIdx.z, pc = blockIdx.x;
    const int p0 = pc * 128;
    const int wm = (wid >> 1) * 64;
    const int wp = (wid & 1) * 64;

    const int kp = g_kp[b];
    const int nchunk = kp >> 6;
    const int* rs = g_rowsrc + b * 384;
    const char* Bb = (const char*)(g_fusedb + (size_t)b * 384 * HWPX);
    const char* Ab = (const char*)(gA2b + (size_t)b * 256 * 384);
    const int kp2 = kp * 2;

    {
        const int cpr = kp >> 3;
        for (int i = t; i < 256 * cpr; i += 256) {
            int m = i / cpr, j = i % cpr;
            cp16(uA + m * kp2 + ((j * 16) ^ ((m & 7) << 4)),
                 Ab + (size_t)m * kp2 + j * 16);
        }
    }
    auto loadB = [&](int buf, int kc0) {
        uint32_t dst = uB + buf * BSZ;
#pragma unroll
        for (int i = t; i < KC * 16; i += 256) {
            int k = i >> 4, j = i & 15;
            int row = rs[kc0 + k];
            cp16(dst + k * BROW + ((j * 16) ^ ((k & 7) << 4)),
                 Bb + ((size_t)row * HWPX + p0) * 2 + j * 16);
        }
    };
    loadB(0, 0);
    cp_commit();
    if (nchunk > 1) { loadB(1, KC); cp_commit(); }

    float acc[4][8][4];
#pragma unroll
    for (int mi = 0; mi < 4; mi++)
#pragma unroll
        for (int ni = 0; ni < 8; ni++)
#pragma unroll
            for (int r = 0; r < 4; r++) acc[mi][ni][r] = 0.f;

    const int a_m  = wm + (lane & 15);
    const int a_kb = (lane >> 4) * 16;
    const uint32_t aBase = uA + a_m * kp2;
    const uint32_t aSwz  = (a_m & 7) << 4;
    const int b_k  = lane & 15;
    const int b_nb = wp * 2 + (lane >> 4) * 16;
    const uint32_t bSwzK = (b_k & 7) << 4;

    for (int c = 0; c < nchunk; c++) {
        if (c == nchunk - 1) cp_wait<0>(); else cp_wait<1>();   // R4 race fix
        __syncthreads();
        const uint32_t bb = uB + (c & 1) * BSZ + b_k * BROW;
#pragma unroll
        for (int ks = 0; ks < KC / 16; ks++) {
            const int kB = ks * 32;
            uint32_t bf[4][4];
#pragma unroll
            for (int h = 0; h < 4; h++)
                ldsm_x4_t(bf[h], bb + ks * 16 * BROW + ((b_nb + h * 32) ^ bSwzK));
#pragma unroll
            for (int mi = 0; mi < 4; mi++) {
                uint32_t a[4];
                ldsm_x4(a, aBase + mi * 16 * kp2 +
                           (((c * KC * 2) + kB + a_kb) ^ aSwz));
#pragma unroll
                for (int ni = 0; ni < 8; ni++)
                    mma16816(acc[mi][ni], a, &bf[ni >> 1][(ni & 1) * 2]);
            }
        }
        __syncthreads();
        if (c + 2 < nchunk) { loadB(c & 1, (c + 2) * KC); cp_commit(); }
    }

    const int erow = lane >> 2;
    const int ecol = (lane & 3) * 2;
#pragma unroll
    for (int mi = 0; mi < 4; mi++) {
#pragma unroll
        for (int h = 0; h < 2; h++) {
            const int m = wm + mi * 16 + h * 8 + erow;
            const float bv = bias[m];
            const size_t rb = ((size_t)(b * OCH + m)) * HWPX + p0;
#pragma unroll
            for (int ni = 0; ni < 8; ni++) {
                const size_t o = rb + wp + ni * 8 + ecol;
                float2 xr = *(const float2*)&xres[o];
                float2 v;
                v.x = acc[mi][ni][2 * h]     + bv + xr.x;
                v.y = acc[mi][ni][2 * h + 1] + bv + xr.y;
                *(float2*)&out[o] = v;
            }
        }
    }
}

// =====================================================================
// k2a_gap: gap from xmean (side stream). grid 32, warp per m.
// =====================================================================
__global__ __launch_bounds__(256) void k2a_gap(const float* __restrict__ pw1_w,
                                               const float* __restrict__ pw1_b)
{
    __shared__ float sxm[2048];
    const int t = threadIdx.x, wid = t >> 5, lane = t & 31;
    for (int i = t; i < 2048; i += 256) sxm[i] = gXmean[i];
    __syncthreads();
    const int m = blockIdx.x * 8 + wid;
    const float* wr = pw1_w + m * CIN;
    float acc[8] = {0.f, 0.f, 0.f, 0.f, 0.f, 0.f, 0.f, 0.f};
    for (int c = lane; c < CIN; c += 32) {
        float w = wr[c];
#pragma unroll
        for (int bb = 0; bb < 8; bb++) acc[bb] = fmaf(sxm[bb * 256 + c], w, acc[bb]);
    }
#pragma unroll
    for (int bb = 0; bb < 8; bb++) acc[bb] = wred(acc[bb]);
    if (lane == 0) {
        float bv = pw1_b[m];
#pragma unroll
        for (int bb = 0; bb < 8; bb++) g_gapv[bb * 256 + m] = acc[bb] + bv;
    }
}

// =====================================================================
// k2a_gap2: gap2 partial reduce (main, after GEMM1). grid 256.
// =====================================================================
__global__ __launch_bounds__(256) void k2a_gap2()
{
    const int t = threadIdx.x, wid = t >> 5, lane = t & 31;
    const int rr = blockIdx.x * 8 + wid;
    const float4* p4 = (const float4*)(g_gap2_part + (size_t)rr * 128);
    float4 v = p4[lane];
    float a = wred(v.x + v.y + v.z + v.w);
    if (lane == 0) g_gap2v[rr] = a * (1.f / (float)HWPX);
}

// =====================================================================
// k2b: fc1. grid 64, warp per j.
// =====================================================================
__global__ __launch_bounds__(256) void k2b(const float* __restrict__ fc1_w,
                                           const float* __restrict__ fc1_b)
{
    __shared__ float sgap[2048];
    const int t = threadIdx.x, wid = t >> 5, lane = t & 31;
    for (int i = t; i < 2048; i += 256) sgap[i] = g_gapv[i];
    __syncthreads();
    const int j = blockIdx.x * 8 + wid;
    const float* wr = fc1_w + j * MCH;
    float acc[8] = {0.f, 0.f, 0.f, 0.f, 0.f, 0.f, 0.f, 0.f};
    for (int c = lane; c < MCH; c += 32) {
        float w = wr[c];
#pragma unroll
        for (int bb = 0; bb < 8; bb++) acc[bb] = fmaf(sgap[bb * 256 + c], w, acc[bb]);
    }
#pragma unroll
    for (int bb = 0; bb < 8; bb++) acc[bb] = wred(acc[bb]);
    if (lane == 0) {
        float bv = fc1_b[j];
#pragma unroll
        for (int bb = 0; bb < 8; bb++) g_hidv[bb * 512 + j] = fmaxf(acc[bb] + bv, 0.f);
    }
}

// =====================================================================
// k2c: fc2 + sigmoid. grid 32, warp per j.
// =====================================================================
__global__ __launch_bounds__(256) void k2c(const float* __restrict__ fc2_w,
                                           const float* __restrict__ fc2_b)
{
    __shared__ float shid[4096];
    const int t = threadIdx.x, wid = t >> 5, lane = t & 31;
    for (int i = t; i < 4096; i += 256) shid[i] = g_hidv[i];
    __syncthreads();
    const int j = blockIdx.x * 8 + wid;
    const float* wr = fc2_w + j * 512;
    float acc[8] = {0.f, 0.f, 0.f, 0.f, 0.f, 0.f, 0.f, 0.f};
    for (int c = lane; c < 512; c += 32) {
        float w = wr[c];
#pragma unroll
        for (int bb = 0; bb < 8; bb++) acc[bb] = fmaf(shid[bb * 512 + c], w, acc[bb]);
    }
#pragma unroll
    for (int bb = 0; bb < 8; bb++) acc[bb] = wred(acc[bb]);
    if (lane == 0) {
        float bv = fc2_b[j];
#pragma unroll
        for (int bb = 0; bb < 8; bb++)
            g_scorev[bb * 256 + j] = 1.f / (1.f + expf(-(acc[bb] + bv)));
    }
}

// =====================================================================
// k2d_mask: top-k mask + sparsity metadata. grid 8.
// =====================================================================
__global__ __launch_bounds__(256) void k2d_mask()
{
    __shared__ float ssc[256], smask[128];
    const int t = threadIdx.x;
    const int bb = blockIdx.x;

    ssc[t] = g_scorev[bb * 256 + t];
    __syncthreads();

    if (t < KSEL) {
        float sc = ssc[t];
        int cnt = 0;
        for (int j = 0; j < MCH; j++) {
            float sj = ssc[j];
            cnt += (sj > sc) || (sj == sc && j < t);
        }
        float mk = (cnt < KSEL) ? 1.f : 0.f;
        smask[t] = mk;
        g_maskv[bb * KSEL + t] = mk;
    }
    __syncthreads();

    if (t < 128) {
        int pos = 0, katot = 0, padc = -1;
        for (int j = 0; j < 128; j++) {
            int a = (smask[j] > 0.f);
            katot += a;
            if (j < t) pos += a;
            if (!a && padc < 0) padc = j;
        }
        if (smask[t] > 0.f) {
#pragma unroll
            for (int g = 0; g < 3; g++)
                g_rowsrc[bb * 384 + g * katot + pos] = g * 128 + t;
        }
        int kp = ((3 * katot + 63) >> 6) << 6;
        if (kp == 0) kp = 64;
        int npad = kp - 3 * katot;
        if (t < npad) g_rowsrc[bb * 384 + 3 * katot + t] = (padc >= 0 ? padc : 0);
        if (t == 0) { g_kp[bb] = kp; g_padch[bb] = padc; }
    }
}

// =====================================================================
// k2d_wts: offsets (gap2) + effective dw weights (mask). grid 64.
// =====================================================================
__global__ __launch_bounds__(256) void k2d_wts(const float* __restrict__ off_w,
                                               const float* __restrict__ off_b,
                                               const float* __restrict__ dw3,
                                               const float* __restrict__ dw5,
                                               const float* __restrict__ dw7)
{
    __shared__ float sg2[256], smask[128], sscl[3], ssht[3];
    const int t = threadIdx.x, wid = t >> 5, lane = t & 31;
    const int bb = blockIdx.x >> 3, slice = blockIdx.x & 7;

    sg2[t] = g_gap2v[bb * 256 + t];
    if (t < 128) smask[t] = g_maskv[bb * KSEL + t];
    __syncthreads();

    if (wid < 6) {
        const int r = wid;
        const float* wr = off_w + r * MCH;
        float a = 0.f;
        for (int c = lane; c < MCH; c += 32) a = fmaf(sg2[c], wr[c], a);
        a = wred(a);
        if (lane == 0) {
            float o = tanhf(a + off_b[r]);
            if ((r & 1) == 0) sscl[r >> 1] = 1.f / (1.f + expf(-o));
            else              ssht[r >> 1] = tanhf(o);
        }
    }
    __syncthreads();

    for (int i = slice * 256 + t; i < 1152; i += 2048) {
        int c = i / 9;
        g_w3[bb * 1152 + i] = fmaf(dw3[i], 1.f + sscl[0], ssht[0]) * smask[c];
    }
    for (int i = slice * 256 + t; i < 3200; i += 2048) {
        int c = i / 25;
        g_w5[bb * 3200 + i] = fmaf(dw5[i], 1.f + sscl[1], ssht[1]) * smask[c];
    }
    for (int i = slice * 256 + t; i < 6272; i += 2048) {
        int c = i / 49;
        g_w7[bb * 6272 + i] = fmaf(dw7[i], 1.f + sscl[2], ssht[2]) * smask[c];
    }
}

// =====================================================================
// kprep2: per-batch gathered A' (side stream, after k2d_mask). grid (256, 8).
// =====================================================================
__global__ __launch_bounds__(256) void kprep2(const float* __restrict__ pw_w)
{
    const int m = blockIdx.x, b = blockIdx.y;
    const int kp = g_kp[b];
    const int* rs = g_rowsrc + b * 384;
    __nv_bfloat16* dst = gA2b + (size_t)b * 256 * 384 + (size_t)m * kp;
    const float* src = pw_w + (size_t)m * 768;
    for (int kk = threadIdx.x; kk < kp; kk += 256)
        dst[kk] = __float2bfloat16(src[rs[kk]]);
}

// =====================================================================
// k3 (protected): scalar dwconv, masked-channel skip.
// =====================================================================
__global__ __launch_bounds__(256) void k3_dwconv()
{
    __shared__ float s[38][40];
    __shared__ float sw[84];

    const int b = blockIdx.z;
    const int c = blockIdx.y;
    const int tile = blockIdx.x;
    const int ty0 = (tile >> 2) * 32;
    const int tx0 = (tile & 3) * 32;
    const int t = threadIdx.x;

    const int py  = t >> 3;
    const int px0 = (t & 7) * 4;
    const size_t obase = ((size_t)(b * (3 * KSEL) + c)) * HWPX + (size_t)(ty0 + py) * WW + tx0 + px0;

    if (g_maskv[b * KSEL + c] == 0.f) {
        if (c == g_padch[b]) {
            const uint2 z = make_uint2(0u, 0u);
            *(uint2*)&g_fusedb[obase] = z;
        }
        return;
    }

    const __nv_bfloat16* in = g_selb + ((size_t)(b * KSEL + c)) * HWPX;

    for (int i = t; i < 38 * 38; i += 256) {
        int r = i / 38, cc = i % 38;
        int gy = ty0 + r - 3, gx = tx0 + cc - 3;
        s[r][cc] = (gy >= 0 && gy < HH && gx >= 0 && gx < WW) ? __bfloat162float(in[gy * WW + gx]) : 0.f;
    }
    if (t < 9)        sw[t] = g_w3[(b * KSEL + c) * 9 + t];
    else if (t < 34)  sw[t] = g_w5[(b * KSEL + c) * 25 + (t - 9)];
    else if (t < 83)  sw[t] = g_w7[(b * KSEL + c) * 49 + (t - 34)];
    __syncthreads();

    float a3[4] = {0.f, 0.f, 0.f, 0.f};
    float a5[4] = {0.f, 0.f, 0.f, 0.f};
    float a7[4] = {0.f, 0.f, 0.f, 0.f};

#pragma unroll
    for (int dy = 0; dy < 7; dy++) {
        const float* row = &s[py + dy][0];
        float4 v0 = *(const float4*)&row[px0];
        float4 v1 = *(const float4*)&row[px0 + 4];
        float4 v2 = *(const float4*)&row[px0 + 8];
        float w[12] = {v0.x, v0.y, v0.z, v0.w, v1.x, v1.y, v1.z, v1.w,
                       v2.x, v2.y, v2.z, v2.w};
#pragma unroll
        for (int dx = 0; dx < 7; dx++) {
            float wt = sw[34 + dy * 7 + dx];
#pragma unroll
            for (int j = 0; j < 4; j++) a7[j] = fmaf(w[j + dx], wt, a7[j]);
        }
        if (dy >= 1 && dy <= 5) {
#pragma unroll
            for (int dx = 0; dx < 5; dx++) {
                float wt = sw[9 + (dy - 1) * 5 + dx];
#pragma unroll
                for (int j = 0; j < 4; j++) a5[j] = fmaf(w[j + 1 + dx], wt, a5[j]);
            }
        }
        if (dy >= 2 && dy <= 4) {
#pragma unroll
            for (int dx = 0; dx < 3; dx++) {
                float wt = sw[(dy - 2) * 3 + dx];
#pragma unroll
                for (int j = 0; j < 4; j++) a3[j] = fmaf(w[j + 2 + dx], wt, a3[j]);
            }
        }
    }

    {
        __nv_bfloat162 p0 = __floats2bfloat162_rn(a3[0], a3[1]);
        __nv_bfloat162 p1 = __floats2bfloat162_rn(a3[2], a3[3]);
        *(uint2*)&g_fusedb[obase] = make_uint2(*(uint32_t*)&p0, *(uint32_t*)&p1);
        p0 = __floats2bfloat162_rn(a5[0], a5[1]);
        p1 = __floats2bfloat162_rn(a5[2], a5[3]);
        *(uint2*)&g_fusedb[obase + (size_t)KSEL * HWPX] = make_uint2(*(uint32_t*)&p0, *(uint32_t*)&p1);
        p0 = __floats2bfloat162_rn(a7[0], a7[1]);
        p1 = __floats2bfloat162_rn(a7[2], a7[3]);
        *(uint2*)&g_fusedb[obase + (size_t)2 * KSEL * HWPX] = make_uint2(*(uint32_t*)&p0, *(uint32_t*)&p1);
    }
}

// =====================================================================
extern "C" void kernel_launch(void* const* d_in, const int* in_sizes, int n_in,
                              void* d_out, int out_size)
{
    const float* x     = (const float*)d_in[0];
    const float* pw1_w = (const float*)d_in[1];
    const float* pw1_b = (const float*)d_in[2];
    const float* fc1_w = (const float*)d_in[3];
    const float* fc1_b = (const float*)d_in[4];
    const float* fc2_w = (const float*)d_in[5];
    const float* fc2_b = (const float*)d_in[6];
    const float* off_w = (const float*)d_in[7];
    const float* off_b = (const float*)d_in[8];
    const float* dw3   = (const float*)d_in[9];
    const float* dw5   = (const float*)d_in[10];
    const float* dw7   = (const float*)d_in[11];
    const float* pw_w  = (const float*)d_in[12];
    const float* pw_b  = (const float*)d_in[13];
    float* out = (float*)d_out;

    const int smem1 = 256 * 256 * 2 + 2 * 16384 + 2 * 256 * 4 + 256;
    const int smem2 = 256 * 384 * 2 + 2 * 16384 + 256;
    cudaFuncSetAttribute((const void*)kgemm<256, 1>, cudaFuncAttributeMaxDynamicSharedMemorySize, smem1);
    cudaFuncSetAttribute((const void*)kgemm2s, cudaFuncAttributeMaxDynamicSharedMemorySize, smem2);

    __nv_bfloat16 *gA1p, *gXbp;
    cudaGetSymbolAddress((void**)&gA1p, gA1);
    cudaGetSymbolAddress((void**)&gXbp, gXb);

    // one-time side stream + events (host resources only; identical launched
    // work on every call, so determinism holds)
    static cudaStream_t s2 = nullptr;
    static cudaEvent_t ev1 = nullptr, ev2 = nullptr;
    if (s2 == nullptr) {
        cudaStreamCreateWithFlags(&s2, cudaStreamNonBlocking);
        cudaEventCreateWithFlags(&ev1, cudaEventDisableTiming);
        cudaEventCreateWithFlags(&ev2, cudaEventDisableTiming);
    }

    // main: kprep (gA1 ready before GEMM1) then kxc, then fork
    kprep<<<256, 256>>>(pw1_w);
    kxc<<<BATCH * CIN, 256>>>(x);
    cudaEventRecord(ev1, 0);

    // side stream (joins capture via ev1): score chain + A-gather,
    // concurrent with GEMM1 on main
    cudaStreamWaitEvent(s2, ev1, 0);
    k2a_gap<<<32, 256, 0, s2>>>(pw1_w, pw1_b);
    k2b<<<64, 256, 0, s2>>>(fc1_w, fc1_b);
    k2c<<<32, 256, 0, s2>>>(fc2_w, fc2_b);
    k2d_mask<<<8, 256, 0, s2>>>();
    kprep2<<<dim3(256, BATCH), 256, 0, s2>>>(pw_w);
    cudaEventRecord(ev2, s2);

    // main: GEMM1 -> gap2 -> join -> weights -> dwconv -> GEMM2
    kgemm<256, 1><<<dim3(128, 1, BATCH), 256, smem1>>>(gA1p, gXbp, pw1_b, nullptr, nullptr);
    k2a_gap2<<<256, 256>>>();
    cudaStreamWaitEvent(0, ev2, 0);
    k2d_wts<<<64, 256>>>(off_w, off_b, dw3, dw5, dw7);
    k3_dwconv<<<dim3(16, KSEL, BATCH), 256>>>();
    kgemm2s<<<dim3(128, 1, BATCH), 256, smem2>>>(pw_b, x, out);
}